// round 5
// baseline (speedup 1.0000x reference)
#include <cuda_runtime.h>
#include <math.h>

#define Bn   2
#define Cc   256
#define Hh   56
#define Ww   56
#define Ll   3136
#define CrD  64
#define Gg   16
#define KKt  49
#define M2   784
#define OUT_OFF (Bn*Cc*Ll)

__device__ float g_t[Bn*CrD*Ll];
__device__ float g_scale[CrD];
__device__ float g_shift[CrD];

// Compile-time tap-offset table: tab[v*49+kkp] = dc*512 + di*64 + dj
struct TabT { int v[16 * KKt]; };
__host__ __device__ constexpr TabT make_tab() {
    TabT t{};
    for (int v = 0; v < 16; v++)
        for (int kkp = 0; kkp < KKt; kkp++) {
            int s  = kkp * Gg + v;
            int dc = s / KKt;
            int tp = s - dc * KKt;
            int r7 = tp / 7;
            int di = r7 - 3;
            int dj = tp - r7 * 7 - 3;
            t.v[v * KKt + kkp] = dc * 512 + di * 64 + dj;
        }
    return t;
}
__constant__ TabT c_tab = make_tab();

// ---------------------------------------------------------------------------
// GEMM1: T[b][m][n] = sum_k W1[m][k] * X[b][k][n]        (no bias: BN cancels it)
// M=64, K=256, N=3136. BM=64, BN=16, BK=64. grid (196,1,2), 256 threads.
// Thread (ty=m 0..63, tx=n-quad 0..3): micro 1x4.
// ---------------------------------------------------------------------------
__global__ __launch_bounds__(256)
void gemm1_kernel(const float* __restrict__ W,
                  const float* __restrict__ X,
                  float* __restrict__ T)
{
    __shared__ float Wm[64][68];   // [m][k]
    __shared__ float As[64][20];   // [k][n]

    int b   = blockIdx.z;
    int bn0 = blockIdx.x * 16;
    int tid = threadIdx.x;
    int tx  = tid & 3;
    int ty  = tid >> 2;

    const float* Xb = X + (size_t)b * Cc * Ll;
    float a0 = 0.f, a1 = 0.f, a2 = 0.f, a3 = 0.f;

    for (int k0 = 0; k0 < Cc; k0 += 64) {
#pragma unroll
        for (int i = 0; i < 4; i++) {
            int idx = tid + i * 256;
            int m   = idx >> 4;
            int k4  = idx & 15;
            float4 v = *(const float4*)&W[(size_t)m * Cc + k0 + k4 * 4];
            *(float4*)&Wm[m][k4 * 4] = v;
        }
        {
            int kk = tid >> 2;
            int n4 = tid & 3;
            float4 v = *(const float4*)&Xb[(size_t)(k0 + kk) * Ll + bn0 + n4 * 4];
            *(float4*)&As[kk][n4 * 4] = v;
        }
        __syncthreads();
#pragma unroll 16
        for (int kk = 0; kk < 64; kk++) {
            float4 a4 = *(const float4*)&As[kk][tx * 4];
            float  w  = Wm[ty][kk];
            a0 = fmaf(w, a4.x, a0);
            a1 = fmaf(w, a4.y, a1);
            a2 = fmaf(w, a4.z, a2);
            a3 = fmaf(w, a4.w, a3);
        }
        __syncthreads();
    }
    *(float4*)&T[((size_t)b * CrD + ty) * Ll + bn0 + tx * 4] =
        make_float4(a0, a1, a2, a3);
}

// ---------------------------------------------------------------------------
// BN batch stats over g_t -> folded scale/shift.
// ---------------------------------------------------------------------------
__global__ void bn_stats_kernel(const float* __restrict__ gamma,
                                const float* __restrict__ beta)
{
    int ch  = blockIdx.x;
    int tid = threadIdx.x;
    double ds = 0.0, ds2 = 0.0;
    for (int i = tid; i < Bn * Ll; i += 256) {
        int b = i / Ll;
        int l = i - b * Ll;
        float v = g_t[((size_t)b * CrD + ch) * Ll + l];
        ds  += v;
        ds2 += (double)v * v;
    }
    __shared__ double sh[256], sh2[256];
    sh[tid] = ds; sh2[tid] = ds2;
    __syncthreads();
    for (int o = 128; o > 0; o >>= 1) {
        if (tid < o) { sh[tid] += sh[tid + o]; sh2[tid] += sh2[tid + o]; }
        __syncthreads();
    }
    if (tid == 0) {
        double n    = (double)(Bn * Ll);
        double mean = sh[0] / n;
        double var  = sh2[0] / n - mean * mean;
        float rstd  = rsqrtf((float)var + 1e-5f);
        float sc    = gamma[ch] * rstd;
        g_scale[ch] = sc;
        g_shift[ch] = beta[ch] - (float)mean * sc;
    }
}

// ---------------------------------------------------------------------------
// GEMM2: Kout[b][m][n] = sum_k W2[m][k] * relu(bn(T[b][k][n])) + b2[m]
// M=784, K=64 (fully smem-resident, one sync), N=3136.
// BM=128, BN=64. grid (49,7,2), 256 threads, micro 8x4.
// Dynamic smem: Wm[128][69] (scalar-stored, bank-clean reads), As[64][68].
// ---------------------------------------------------------------------------
#define WMP 69
#define ASP 68
#define WM_FLOATS (128 * WMP)
#define G2_SMEM ((WM_FLOATS + 64 * ASP) * 4)

extern __shared__ float s_g2[];

__global__ __launch_bounds__(256, 4)
void gemm2_kernel(const float* __restrict__ W2,
                  const float* __restrict__ T,
                  const float* __restrict__ b2,
                  float* __restrict__ Kout)
{
    float* Wm = s_g2;                 // [128][WMP]
    float* As = s_g2 + WM_FLOATS;     // [64][ASP]

    int b   = blockIdx.z;
    int bm0 = blockIdx.y * 128;
    int bn0 = blockIdx.x * 64;
    int tid = threadIdx.x;
    int tx  = tid & 15;
    int ty  = tid >> 4;

    // load W2 tile 128 x 64 (scalar stores; pitch 69 for conflict-free reads)
#pragma unroll
    for (int i = 0; i < 8; i++) {
        int idx = tid + i * 256;
        int m   = idx >> 4;
        int k4  = idx & 15;
        int gm  = bm0 + m;
        float4 v = make_float4(0.f, 0.f, 0.f, 0.f);
        if (gm < M2)
            v = *(const float4*)&W2[(size_t)gm * CrD + k4 * 4];
        float* w = &Wm[m * WMP + k4 * 4];
        w[0] = v.x; w[1] = v.y; w[2] = v.z; w[3] = v.w;
    }
    // load A tile 64 x 64 with fused BN+ReLU
#pragma unroll
    for (int i = 0; i < 4; i++) {
        int idx = tid + i * 256;
        int kk  = idx >> 4;
        int n4  = idx & 15;
        float4 v = *(const float4*)&T[((size_t)b * CrD + kk) * Ll + bn0 + n4 * 4];
        float sc = g_scale[kk], sh = g_shift[kk];
        v.x = fmaxf(fmaf(v.x, sc, sh), 0.f);
        v.y = fmaxf(fmaf(v.y, sc, sh), 0.f);
        v.z = fmaxf(fmaf(v.z, sc, sh), 0.f);
        v.w = fmaxf(fmaf(v.w, sc, sh), 0.f);
        *(float4*)&As[kk * ASP + n4 * 4] = v;
    }
    __syncthreads();

    float acc[8][4];
#pragma unroll
    for (int i = 0; i < 8; i++)
#pragma unroll
        for (int j = 0; j < 4; j++) acc[i][j] = 0.f;

#pragma unroll 8
    for (int kk = 0; kk < 64; kk++) {
        float4 a4 = *(const float4*)&As[kk * ASP + tx * 4];
#pragma unroll
        for (int i = 0; i < 8; i++) {
            float w = Wm[(ty * 8 + i) * WMP + kk];
            acc[i][0] = fmaf(w, a4.x, acc[i][0]);
            acc[i][1] = fmaf(w, a4.y, acc[i][1]);
            acc[i][2] = fmaf(w, a4.z, acc[i][2]);
            acc[i][3] = fmaf(w, a4.w, acc[i][3]);
        }
    }

#pragma unroll
    for (int i = 0; i < 8; i++) {
        int gm = bm0 + ty * 8 + i;
        if (gm < M2) {
            float bb = b2[gm];
            float4 v = make_float4(acc[i][0] + bb, acc[i][1] + bb,
                                   acc[i][2] + bb, acc[i][3] + bb);
            *(float4*)&Kout[((size_t)b * M2 + gm) * Ll + bn0 + tx * 4] = v;
        }
    }
}

// ---------------------------------------------------------------------------
// Involution (R3 structure, tap table moved to __constant__).
// ---------------------------------------------------------------------------
extern __shared__ float s_xs[];

__global__ __launch_bounds__(1024, 1)
void involution_kernel(const float* __restrict__ x,
                       const float* __restrict__ kgen,
                       float* __restrict__ out)
{
    float* xs = s_xs;                 // 64*8*64 = 32768 floats (128 KB)

    const int tid = threadIdx.x;
    const int uq  = blockIdx.y;
    const int b   = blockIdx.z;
    const int l0  = blockIdx.x * 64;
    const int y0  = l0 / Ww;

    // stage x tile: channels [uq*64, uq*64+64), rows y0-3..y0+4, cols -3..60
    {
        const float* xb = x + ((size_t)b * Cc + uq * 64) * Ll;
#pragma unroll
        for (int i = 0; i < 32; i++) {
            int idx  = tid + i * 1024;
            int cl   = idx >> 9;
            int rem  = idx & 511;
            int yrel = rem >> 6;
            int j    = rem & 63;
            int yy   = y0 - 3 + yrel;
            int xcol = j - 3;
            float v = 0.f;
            if ((unsigned)yy < Hh && (unsigned)xcol < Ww)
                v = xb[(size_t)cl * Ll + yy * Ww + xcol];
            xs[idx] = v;
        }
    }
    __syncthreads();

    const int v    = tid >> 6;
    const int lofs = tid & 63;
    const int l    = l0 + lofs;
    const int y    = l / Ww;
    const int xp   = l - y * Ww;
    const int thr_base = (y - y0 + 3) * 64 + (xp + 3);

    const float* kb = kgen + (size_t)b * M2 * Ll + (size_t)v * Ll + l;
    const int*   tv = c_tab.v + v * KKt;

    float acc0 = 0.f, acc1 = 0.f, acc2 = 0.f, acc3 = 0.f;

#pragma unroll 7
    for (int kkp = 0; kkp < KKt; kkp++) {
        float kv = kb[(size_t)(kkp * Gg) * Ll];
        int   a  = tv[kkp] + thr_base;
        acc0 = fmaf(kv, xs[a        ], acc0);
        acc1 = fmaf(kv, xs[a + 8192 ], acc1);
        acc2 = fmaf(kv, xs[a + 16384], acc2);
        acc3 = fmaf(kv, xs[a + 24576], acc3);
    }

    float* ob = out + (size_t)b * Cc * Ll + (size_t)((uq * 4) * Gg + v) * Ll + l;
    ob[0 * Gg * Ll] = acc0;
    ob[1 * Gg * Ll] = acc1;
    ob[2 * Gg * Ll] = acc2;
    ob[3 * Gg * Ll] = acc3;
}

// ---------------------------------------------------------------------------
extern "C" void kernel_launch(void* const* d_in, const int* in_sizes, int n_in,
                              void* d_out, int out_size)
{
    const float* x     = (const float*)d_in[0];
    const float* w1    = (const float*)d_in[1];
    const float* gamma = (const float*)d_in[3];
    const float* beta  = (const float*)d_in[4];
    const float* w2    = (const float*)d_in[5];
    const float* b2    = (const float*)d_in[6];

    float* out  = (float*)d_out;
    float* kgen = out + OUT_OFF;

    float* t_ptr = nullptr;
    cudaGetSymbolAddress((void**)&t_ptr, g_t);

    static int configured = 0;
    if (!configured) {
        cudaFuncSetAttribute(gemm2_kernel,
                             cudaFuncAttributeMaxDynamicSharedMemorySize,
                             G2_SMEM);
        cudaFuncSetAttribute(involution_kernel,
                             cudaFuncAttributeMaxDynamicSharedMemorySize,
                             32768 * 4);
        configured = 1;
    }

    // 1) conv1 (b1 dropped: BN cancels per-channel constant shift)
    {
        dim3 grid(Ll / 16, 1, Bn);
        gemm1_kernel<<<grid, 256>>>(w1, x, t_ptr);
    }
    // 2) BN batch stats
    bn_stats_kernel<<<CrD, 256>>>(gamma, beta);

    // 3) conv2 + fused BN/ReLU, single-stage K=64
    {
        dim3 grid(Ll / 64, (M2 + 127) / 128, Bn);
        gemm2_kernel<<<grid, 256, G2_SMEM>>>(w2, t_ptr, b2, kgen);
    }
    // 4) involution
    {
        dim3 grid(Ll / 64, 4, Bn);
        involution_kernel<<<grid, 1024, 32768 * 4>>>(x, kgen, out);
    }
}

// round 9
// speedup vs baseline: 1.0373x; 1.0373x over previous
#include <cuda_runtime.h>
#include <math.h>

#define Bn   2
#define Cc   256
#define Hh   56
#define Ww   56
#define Ll   3136
#define CrD  64
#define Gg   16
#define KKt  49
#define M2   784
#define OUT_OFF (Bn*Cc*Ll)

__device__ float g_t[Bn*CrD*Ll];
__device__ float g_scale[CrD];
__device__ float g_shift[CrD];

// tap table: tab[v*49+kkp] = dc*512 + di*64 + dj   (xs layout [ch][8 rows][64 cols])
struct TabT { int v[16 * KKt]; };
__host__ __device__ constexpr TabT make_tab() {
    TabT t{};
    for (int v = 0; v < 16; v++)
        for (int kkp = 0; kkp < KKt; kkp++) {
            int s  = kkp * Gg + v;
            int dc = s / KKt;
            int tp = s - dc * KKt;
            int r7 = tp / 7;
            int di = r7 - 3;
            int dj = tp - r7 * 7 - 3;
            t.v[v * KKt + kkp] = dc * 512 + di * 64 + dj;
        }
    return t;
}
__constant__ TabT c_tab = make_tab();

// ---------------------------------------------------------------------------
// GEMM1: T[b][m][n] = sum_k W1[m][k] * X[b][k][n]   (b1 dropped: BN cancels it)
// M=64, K=256, N=3136. BM=32, BN=32, BK=64. grid (98,2,2)=392. 256 thr, micro 2x2.
// Pitch 36 (multiple of 4 -> float4 stores aligned; float2 reads conflict-free).
// ---------------------------------------------------------------------------
#define WP1 36
__global__ __launch_bounds__(256)
void gemm1_kernel(const float* __restrict__ W,
                  const float* __restrict__ X,
                  float* __restrict__ T)
{
    __shared__ float Wm[64 * WP1];   // [k][m]
    __shared__ float As[64 * WP1];   // [k][n]

    int b   = blockIdx.z;
    int bm0 = blockIdx.y * 32;
    int bn0 = blockIdx.x * 32;
    int tid = threadIdx.x;
    int tx  = tid & 15;     // n-pair
    int ty  = tid >> 4;     // m-pair

    const float* Xb = X + (size_t)b * Cc * Ll;
    float acc[2][2] = {{0.f, 0.f}, {0.f, 0.f}};

    for (int k0 = 0; k0 < Cc; k0 += 64) {
        // W tile: 32m x 64k, transpose-store to [k][m] (scalar stores)
#pragma unroll
        for (int i = 0; i < 2; i++) {
            int idx = tid + i * 256;       // 0..511
            int m   = idx >> 4;            // 0..31
            int k4  = idx & 15;
            float4 v = *(const float4*)&W[(size_t)(bm0 + m) * Cc + k0 + k4 * 4];
            Wm[(k4 * 4 + 0) * WP1 + m] = v.x;
            Wm[(k4 * 4 + 1) * WP1 + m] = v.y;
            Wm[(k4 * 4 + 2) * WP1 + m] = v.z;
            Wm[(k4 * 4 + 3) * WP1 + m] = v.w;
        }
        // A tile: 64k x 32n (float4 stores, pitch 36 keeps 16B alignment)
#pragma unroll
        for (int i = 0; i < 2; i++) {
            int idx = tid + i * 256;
            int kk  = idx >> 3;            // 0..63
            int n4  = idx & 7;
            float4 v = *(const float4*)&Xb[(size_t)(k0 + kk) * Ll + bn0 + n4 * 4];
            *(float4*)&As[kk * WP1 + n4 * 4] = v;
        }
        __syncthreads();
#pragma unroll 8
        for (int kk = 0; kk < 64; kk++) {
            float2 w2 = *(const float2*)&Wm[kk * WP1 + ty * 2];
            float2 a2 = *(const float2*)&As[kk * WP1 + tx * 2];
            acc[0][0] = fmaf(w2.x, a2.x, acc[0][0]);
            acc[0][1] = fmaf(w2.x, a2.y, acc[0][1]);
            acc[1][0] = fmaf(w2.y, a2.x, acc[1][0]);
            acc[1][1] = fmaf(w2.y, a2.y, acc[1][1]);
        }
        __syncthreads();
    }
#pragma unroll
    for (int i = 0; i < 2; i++) {
        int ch = bm0 + ty * 2 + i;
        *(float2*)&T[((size_t)b * CrD + ch) * Ll + bn0 + tx * 2] =
            make_float2(acc[i][0], acc[i][1]);
    }
}

// ---------------------------------------------------------------------------
// BN batch stats over g_t -> folded scale/shift (float4 reads).
// ---------------------------------------------------------------------------
__global__ void bn_stats_kernel(const float* __restrict__ gamma,
                                const float* __restrict__ beta)
{
    int ch  = blockIdx.x;
    int tid = threadIdx.x;
    double ds = 0.0, ds2 = 0.0;
    const int F4 = Ll / 4;             // 784 per batch
    for (int i = tid; i < Bn * F4; i += 256) {
        int b  = i / F4;
        int l4 = i - b * F4;
        float4 v = *(const float4*)&g_t[((size_t)b * CrD + ch) * Ll + l4 * 4];
        ds  += (double)v.x + v.y + v.z + v.w;
        ds2 += (double)v.x * v.x + (double)v.y * v.y
             + (double)v.z * v.z + (double)v.w * v.w;
    }
    __shared__ double sh[256], sh2[256];
    sh[tid] = ds; sh2[tid] = ds2;
    __syncthreads();
    for (int o = 128; o > 0; o >>= 1) {
        if (tid < o) { sh[tid] += sh[tid + o]; sh2[tid] += sh2[tid + o]; }
        __syncthreads();
    }
    if (tid == 0) {
        double n    = (double)(Bn * Ll);
        double mean = sh[0] / n;
        double var  = sh2[0] / n - mean * mean;
        float rstd  = rsqrtf((float)var + 1e-5f);
        float sc    = gamma[ch] * rstd;
        g_scale[ch] = sc;
        g_shift[ch] = beta[ch] - (float)mean * sc;
    }
}

// ---------------------------------------------------------------------------
// GEMM2: Kout = W2 @ relu(bn(T)) + b2.  M=784, K=64 (one stage), N=3136.
// BM=128, BN=64, 256 thr, micro 8x4, inner in 4-k chunks with LDS.128 w loads.
// ---------------------------------------------------------------------------
#define WMP 72
#define ASP 68
#define WM_FLOATS (128 * WMP)
#define G2_SMEM ((WM_FLOATS + 64 * ASP) * 4)

extern __shared__ float s_g2[];

__global__ __launch_bounds__(256, 4)
void gemm2_kernel(const float* __restrict__ W2,
                  const float* __restrict__ T,
                  const float* __restrict__ b2,
                  float* __restrict__ Kout)
{
    float* Wm = s_g2;               // [128][72]
    float* As = s_g2 + WM_FLOATS;   // [64][68]

    int b   = blockIdx.z;
    int bm0 = blockIdx.y * 128;
    int bn0 = blockIdx.x * 64;
    int tid = threadIdx.x;
    int tx  = tid & 15;
    int ty  = tid >> 4;

    // W2 tile 128 x 64 (direct float4 copy, 16B-aligned pitch 72)
#pragma unroll
    for (int i = 0; i < 8; i++) {
        int idx = tid + i * 256;
        int m   = idx >> 4;
        int k4  = idx & 15;
        int gm  = bm0 + m;
        float4 v = make_float4(0.f, 0.f, 0.f, 0.f);
        if (gm < M2)
            v = *(const float4*)&W2[(size_t)gm * CrD + k4 * 4];
        *(float4*)&Wm[m * WMP + k4 * 4] = v;
    }
    // A tile 64 x 64 + fused BN/ReLU
#pragma unroll
    for (int i = 0; i < 4; i++) {
        int idx = tid + i * 256;
        int kk  = idx >> 4;
        int n4  = idx & 15;
        float4 v = *(const float4*)&T[((size_t)b * CrD + kk) * Ll + bn0 + n4 * 4];
        float sc = g_scale[kk], sh = g_shift[kk];
        v.x = fmaxf(fmaf(v.x, sc, sh), 0.f);
        v.y = fmaxf(fmaf(v.y, sc, sh), 0.f);
        v.z = fmaxf(fmaf(v.z, sc, sh), 0.f);
        v.w = fmaxf(fmaf(v.w, sc, sh), 0.f);
        *(float4*)&As[kk * ASP + n4 * 4] = v;
    }
    __syncthreads();

    float acc[8][4];
#pragma unroll
    for (int i = 0; i < 8; i++)
#pragma unroll
        for (int j = 0; j < 4; j++) acc[i][j] = 0.f;

#pragma unroll 4
    for (int k4 = 0; k4 < 16; k4++) {
        float4 a0 = *(const float4*)&As[(k4 * 4 + 0) * ASP + tx * 4];
        float4 a1 = *(const float4*)&As[(k4 * 4 + 1) * ASP + tx * 4];
        float4 a2 = *(const float4*)&As[(k4 * 4 + 2) * ASP + tx * 4];
        float4 a3 = *(const float4*)&As[(k4 * 4 + 3) * ASP + tx * 4];
#pragma unroll
        for (int i = 0; i < 8; i++) {
            float4 w = *(const float4*)&Wm[(ty * 8 + i) * WMP + k4 * 4];
            acc[i][0] = fmaf(w.x, a0.x, acc[i][0]);
            acc[i][1] = fmaf(w.x, a0.y, acc[i][1]);
            acc[i][2] = fmaf(w.x, a0.z, acc[i][2]);
            acc[i][3] = fmaf(w.x, a0.w, acc[i][3]);
            acc[i][0] = fmaf(w.y, a1.x, acc[i][0]);
            acc[i][1] = fmaf(w.y, a1.y, acc[i][1]);
            acc[i][2] = fmaf(w.y, a1.z, acc[i][2]);
            acc[i][3] = fmaf(w.y, a1.w, acc[i][3]);
            acc[i][0] = fmaf(w.z, a2.x, acc[i][0]);
            acc[i][1] = fmaf(w.z, a2.y, acc[i][1]);
            acc[i][2] = fmaf(w.z, a2.z, acc[i][2]);
            acc[i][3] = fmaf(w.z, a2.w, acc[i][3]);
            acc[i][0] = fmaf(w.w, a3.x, acc[i][0]);
            acc[i][1] = fmaf(w.w, a3.y, acc[i][1]);
            acc[i][2] = fmaf(w.w, a3.z, acc[i][2]);
            acc[i][3] = fmaf(w.w, a3.w, acc[i][3]);
        }
    }

#pragma unroll
    for (int i = 0; i < 8; i++) {
        int gm = bm0 + ty * 8 + i;
        if (gm < M2) {
            float bb = b2[gm];
            float4 v = make_float4(acc[i][0] + bb, acc[i][1] + bb,
                                   acc[i][2] + bb, acc[i][3] + bb);
            *(float4*)&Kout[((size_t)b * M2 + gm) * Ll + bn0 + tx * 4] = v;
        }
    }
}

// ---------------------------------------------------------------------------
// Involution, smem-staged x, vectorized staging.
// xs layout: [cl 0..63][yrel 0..7][col 0..63]; x data at cols 4..59 (xcol+4),
// zero halo at cols 0..3 / 60..63 and OOB rows. 128 KB smem, 1024 threads.
// ---------------------------------------------------------------------------
extern __shared__ float s_xs[];

__global__ __launch_bounds__(1024, 1)
void involution_kernel(const float* __restrict__ x,
                       const float* __restrict__ kgen,
                       float* __restrict__ out)
{
    float* xs = s_xs;
    float4* xs4 = (float4*)s_xs;

    const int tid = threadIdx.x;
    const int uq  = blockIdx.y;
    const int b   = blockIdx.z;
    const int l0  = blockIdx.x * 64;
    const int y0  = l0 / Ww;

    // stage: 8192 float4 slots = 64 cl x 8 rows x 16 quads
    {
        const float* xb = x + ((size_t)b * Cc + uq * 64) * Ll;
#pragma unroll
        for (int i = 0; i < 8; i++) {
            int idx  = tid + i * 1024;
            int cl   = idx >> 7;
            int rem  = idx & 127;
            int yrel = rem >> 4;
            int f4   = rem & 15;
            int yy   = y0 - 3 + yrel;
            float4 v = make_float4(0.f, 0.f, 0.f, 0.f);
            if (f4 >= 1 && f4 <= 14 && (unsigned)yy < Hh)
                v = *(const float4*)&xb[(size_t)cl * Ll + yy * Ww + (f4 - 1) * 4];
            xs4[idx] = v;
        }
    }
    __syncthreads();

    const int v    = tid >> 6;
    const int lofs = tid & 63;
    const int l    = l0 + lofs;
    const int y    = l / Ww;
    const int xp   = l - y * Ww;
    const int thr_base = (y - y0 + 3) * 64 + (xp + 4);

    const float* kb = kgen + (size_t)b * M2 * Ll + (size_t)v * Ll + l;
    const int*   tv = c_tab.v + v * KKt;

    float acc0 = 0.f, acc1 = 0.f, acc2 = 0.f, acc3 = 0.f;

#pragma unroll 7
    for (int kkp = 0; kkp < KKt; kkp++) {
        float kv = kb[(size_t)(kkp * Gg) * Ll];
        int   a  = tv[kkp] + thr_base;
        acc0 = fmaf(kv, xs[a        ], acc0);
        acc1 = fmaf(kv, xs[a + 8192 ], acc1);
        acc2 = fmaf(kv, xs[a + 16384], acc2);
        acc3 = fmaf(kv, xs[a + 24576], acc3);
    }

    float* ob = out + (size_t)b * Cc * Ll + (size_t)((uq * 4) * Gg + v) * Ll + l;
    ob[0 * Gg * Ll] = acc0;
    ob[1 * Gg * Ll] = acc1;
    ob[2 * Gg * Ll] = acc2;
    ob[3 * Gg * Ll] = acc3;
}

// ---------------------------------------------------------------------------
extern "C" void kernel_launch(void* const* d_in, const int* in_sizes, int n_in,
                              void* d_out, int out_size)
{
    const float* x     = (const float*)d_in[0];
    const float* w1    = (const float*)d_in[1];
    const float* gamma = (const float*)d_in[3];
    const float* beta  = (const float*)d_in[4];
    const float* w2    = (const float*)d_in[5];
    const float* b2    = (const float*)d_in[6];

    float* out  = (float*)d_out;
    float* kgen = out + OUT_OFF;

    float* t_ptr = nullptr;
    cudaGetSymbolAddress((void**)&t_ptr, g_t);

    cudaFuncSetAttribute(gemm2_kernel,
                         cudaFuncAttributeMaxDynamicSharedMemorySize, G2_SMEM);
    cudaFuncSetAttribute(involution_kernel,
                         cudaFuncAttributeMaxDynamicSharedMemorySize, 32768 * 4);

    // 1) conv1
    {
        dim3 grid(Ll / 32, 2, Bn);
        gemm1_kernel<<<grid, 256>>>(w1, x, t_ptr);
    }
    // 2) BN batch stats
    bn_stats_kernel<<<CrD, 256>>>(gamma, beta);

    // 3) conv2 + fused BN/ReLU
    {
        dim3 grid(Ll / 64, (M2 + 127) / 128, Bn);
        gemm2_kernel<<<grid, 256, G2_SMEM>>>(w2, t_ptr, b2, kgen);
    }
    // 4) involution
    {
        dim3 grid(Ll / 64, 4, Bn);
        involution_kernel<<<grid, 1024, 32768 * 4>>>(x, kgen, out);
    }
}

// round 10
// speedup vs baseline: 1.1204x; 1.0801x over previous
#include <cuda_runtime.h>
#include <math.h>

#define Bn   2
#define Cc   256
#define Hh   56
#define Ww   56
#define Ll   3136
#define CrD  64
#define Gg   16
#define KKt  49
#define M2   784
#define OUT_OFF (Bn*Cc*Ll)

typedef unsigned long long u64t;

// packed f32x2 helpers (sm_103a FFMA2 pipe — fp32-exact)
#define FMA2(d, a, b) \
    asm("fma.rn.f32x2 %0, %1, %2, %0;" : "+l"(d) : "l"(a), "l"(b))
#define DUP2(u, f) \
    asm("mov.b64 %0, {%1, %1};" : "=l"(u) : "r"(__float_as_uint(f)))
__device__ __forceinline__ float lo32(u64t u) { return __uint_as_float((unsigned)(u & 0xffffffffu)); }
__device__ __forceinline__ float hi32(u64t u) { return __uint_as_float((unsigned)(u >> 32)); }

__device__ float g_t[Bn*CrD*Ll];
__device__ float g_scale[CrD];
__device__ float g_shift[CrD];

// tap table: tab[v*49+kkp] = dc*512 + di*64 + dj   (xs layout [ch][8 rows][64 cols])
struct TabT { int v[16 * KKt]; };
__host__ __device__ constexpr TabT make_tab() {
    TabT t{};
    for (int v = 0; v < 16; v++)
        for (int kkp = 0; kkp < KKt; kkp++) {
            int s  = kkp * Gg + v;
            int dc = s / KKt;
            int tp = s - dc * KKt;
            int r7 = tp / 7;
            int di = r7 - 3;
            int dj = tp - r7 * 7 - 3;
            t.v[v * KKt + kkp] = dc * 512 + di * 64 + dj;
        }
    return t;
}
__constant__ TabT c_tab = make_tab();

// ---------------------------------------------------------------------------
// GEMM1: T[b][m][n] = sum_k W1[m][k] * X[b][k][n]   (b1 dropped: BN cancels it)
// M=64, K=256, N=3136. BM=32, BN=32, BK=64. grid (98,2,2)=392. 256 thr.
// micro 2x2, m-packed f32x2: w-pair is a direct b64 load from Wm[k][m].
// ---------------------------------------------------------------------------
#define WP1 36
__global__ __launch_bounds__(256)
void gemm1_kernel(const float* __restrict__ W,
                  const float* __restrict__ X,
                  float* __restrict__ T)
{
    __shared__ float Wm[64 * WP1];   // [k][m]
    __shared__ float As[64 * WP1];   // [k][n]

    int b   = blockIdx.z;
    int bm0 = blockIdx.y * 32;
    int bn0 = blockIdx.x * 32;
    int tid = threadIdx.x;
    int tx  = tid & 15;     // n-pair
    int ty  = tid >> 4;     // m-pair

    const float* Xb = X + (size_t)b * Cc * Ll;
    u64t acc0 = 0ull, acc1 = 0ull;   // (m0,m1) for n0 / n1

    for (int k0 = 0; k0 < Cc; k0 += 64) {
#pragma unroll
        for (int i = 0; i < 2; i++) {
            int idx = tid + i * 256;
            int m   = idx >> 4;
            int k4  = idx & 15;
            float4 v = *(const float4*)&W[(size_t)(bm0 + m) * Cc + k0 + k4 * 4];
            Wm[(k4 * 4 + 0) * WP1 + m] = v.x;
            Wm[(k4 * 4 + 1) * WP1 + m] = v.y;
            Wm[(k4 * 4 + 2) * WP1 + m] = v.z;
            Wm[(k4 * 4 + 3) * WP1 + m] = v.w;
        }
#pragma unroll
        for (int i = 0; i < 2; i++) {
            int idx = tid + i * 256;
            int kk  = idx >> 3;
            int n4  = idx & 7;
            float4 v = *(const float4*)&Xb[(size_t)(k0 + kk) * Ll + bn0 + n4 * 4];
            *(float4*)&As[kk * WP1 + n4 * 4] = v;
        }
        __syncthreads();
#pragma unroll 8
        for (int kk = 0; kk < 64; kk++) {
            u64t  w2 = *(const u64t*)&Wm[kk * WP1 + ty * 2];   // (w_m0, w_m1)
            float2 a2 = *(const float2*)&As[kk * WP1 + tx * 2];
            u64t an0, an1;
            DUP2(an0, a2.x);
            DUP2(an1, a2.y);
            FMA2(acc0, w2, an0);
            FMA2(acc1, w2, an1);
        }
        __syncthreads();
    }
    // acc0 = (m0n0, m1n0), acc1 = (m0n1, m1n1)
    {
        int ch0 = bm0 + ty * 2;
        *(float2*)&T[((size_t)b * CrD + ch0) * Ll + bn0 + tx * 2] =
            make_float2(lo32(acc0), lo32(acc1));
        *(float2*)&T[((size_t)b * CrD + ch0 + 1) * Ll + bn0 + tx * 2] =
            make_float2(hi32(acc0), hi32(acc1));
    }
}

// ---------------------------------------------------------------------------
// BN batch stats over g_t -> folded scale/shift. FP32 accumulation (6272
// elements/channel, thread-partials ~98 values -> error ~1e-6, well in budget).
// ---------------------------------------------------------------------------
__global__ void bn_stats_kernel(const float* __restrict__ gamma,
                                const float* __restrict__ beta)
{
    int ch  = blockIdx.x;
    int tid = threadIdx.x;
    float fs = 0.f, fs2 = 0.f;
    const int F4 = Ll / 4;             // 784 per batch
    for (int i = tid; i < Bn * F4; i += 256) {
        int b  = i / F4;
        int l4 = i - b * F4;
        float4 v = *(const float4*)&g_t[((size_t)b * CrD + ch) * Ll + l4 * 4];
        fs  += v.x + v.y + v.z + v.w;
        fs2 += v.x * v.x + v.y * v.y + v.z * v.z + v.w * v.w;
    }
    __shared__ float sh[256], sh2[256];
    sh[tid] = fs; sh2[tid] = fs2;
    __syncthreads();
    for (int o = 128; o > 0; o >>= 1) {
        if (tid < o) { sh[tid] += sh[tid + o]; sh2[tid] += sh2[tid + o]; }
        __syncthreads();
    }
    if (tid == 0) {
        float n    = (float)(Bn * Ll);
        float mean = sh[0] / n;
        float var  = sh2[0] / n - mean * mean;
        float rstd = rsqrtf(var + 1e-5f);
        float sc   = gamma[ch] * rstd;
        g_scale[ch] = sc;
        g_shift[ch] = beta[ch] - mean * sc;
    }
}

// ---------------------------------------------------------------------------
// GEMM2: Kout = W2 @ relu(bn(T)) + b2.  M=784, K=64 (one stage), N=3136.
// BM=128, BN=64, 256 thr, micro 8x4. Inner loop n-packed f32x2:
// a as direct b64 loads, w float4 + dup, 64 FFMA2 per 4-k chunk.
// ---------------------------------------------------------------------------
#define WMP 72
#define ASP 68
#define WM_FLOATS (128 * WMP)
#define G2_SMEM ((WM_FLOATS + 64 * ASP) * 4)

extern __shared__ float s_g2[];

__global__ __launch_bounds__(256, 4)
void gemm2_kernel(const float* __restrict__ W2,
                  const float* __restrict__ T,
                  const float* __restrict__ b2,
                  float* __restrict__ Kout)
{
    float* Wm = s_g2;               // [128][72]
    float* As = s_g2 + WM_FLOATS;   // [64][68]

    int b   = blockIdx.z;
    int bm0 = blockIdx.y * 128;
    int bn0 = blockIdx.x * 64;
    int tid = threadIdx.x;
    int tx  = tid & 15;
    int ty  = tid >> 4;

#pragma unroll
    for (int i = 0; i < 8; i++) {
        int idx = tid + i * 256;
        int m   = idx >> 4;
        int k4  = idx & 15;
        int gm  = bm0 + m;
        float4 v = make_float4(0.f, 0.f, 0.f, 0.f);
        if (gm < M2)
            v = *(const float4*)&W2[(size_t)gm * CrD + k4 * 4];
        *(float4*)&Wm[m * WMP + k4 * 4] = v;
    }
#pragma unroll
    for (int i = 0; i < 4; i++) {
        int idx = tid + i * 256;
        int kk  = idx >> 4;
        int n4  = idx & 15;
        float4 v = *(const float4*)&T[((size_t)b * CrD + kk) * Ll + bn0 + n4 * 4];
        float sc = g_scale[kk], sh = g_shift[kk];
        v.x = fmaxf(fmaf(v.x, sc, sh), 0.f);
        v.y = fmaxf(fmaf(v.y, sc, sh), 0.f);
        v.z = fmaxf(fmaf(v.z, sc, sh), 0.f);
        v.w = fmaxf(fmaf(v.w, sc, sh), 0.f);
        *(float4*)&As[kk * ASP + n4 * 4] = v;
    }
    __syncthreads();

    u64t acc[8][2];                  // [m-row][n-half], each = 2 packed n
#pragma unroll
    for (int i = 0; i < 8; i++) { acc[i][0] = 0ull; acc[i][1] = 0ull; }

#pragma unroll 4
    for (int k4 = 0; k4 < 16; k4++) {
        u64t a[4][2];
#pragma unroll
        for (int r = 0; r < 4; r++) {
            const float* ap = &As[(k4 * 4 + r) * ASP + tx * 4];
            a[r][0] = *(const u64t*)(ap);
            a[r][1] = *(const u64t*)(ap + 2);
        }
#pragma unroll
        for (int i = 0; i < 8; i++) {
            float4 w = *(const float4*)&Wm[(ty * 8 + i) * WMP + k4 * 4];
            u64t wd;
            DUP2(wd, w.x);
            FMA2(acc[i][0], wd, a[0][0]);
            FMA2(acc[i][1], wd, a[0][1]);
            DUP2(wd, w.y);
            FMA2(acc[i][0], wd, a[1][0]);
            FMA2(acc[i][1], wd, a[1][1]);
            DUP2(wd, w.z);
            FMA2(acc[i][0], wd, a[2][0]);
            FMA2(acc[i][1], wd, a[2][1]);
            DUP2(wd, w.w);
            FMA2(acc[i][0], wd, a[3][0]);
            FMA2(acc[i][1], wd, a[3][1]);
        }
    }

#pragma unroll
    for (int i = 0; i < 8; i++) {
        int gm = bm0 + ty * 8 + i;
        if (gm < M2) {
            float bb = b2[gm];
            float4 v = make_float4(lo32(acc[i][0]) + bb, hi32(acc[i][0]) + bb,
                                   lo32(acc[i][1]) + bb, hi32(acc[i][1]) + bb);
            *(float4*)&Kout[((size_t)b * M2 + gm) * Ll + bn0 + tx * 4] = v;
        }
    }
}

// ---------------------------------------------------------------------------
// Involution, smem-staged x, vectorized staging (unchanged from best).
// ---------------------------------------------------------------------------
extern __shared__ float s_xs[];

__global__ __launch_bounds__(1024, 1)
void involution_kernel(const float* __restrict__ x,
                       const float* __restrict__ kgen,
                       float* __restrict__ out)
{
    float* xs = s_xs;
    float4* xs4 = (float4*)s_xs;

    const int tid = threadIdx.x;
    const int uq  = blockIdx.y;
    const int b   = blockIdx.z;
    const int l0  = blockIdx.x * 64;
    const int y0  = l0 / Ww;

    {
        const float* xb = x + ((size_t)b * Cc + uq * 64) * Ll;
#pragma unroll
        for (int i = 0; i < 8; i++) {
            int idx  = tid + i * 1024;
            int cl   = idx >> 7;
            int rem  = idx & 127;
            int yrel = rem >> 4;
            int f4   = rem & 15;
            int yy   = y0 - 3 + yrel;
            float4 v = make_float4(0.f, 0.f, 0.f, 0.f);
            if (f4 >= 1 && f4 <= 14 && (unsigned)yy < Hh)
                v = *(const float4*)&xb[(size_t)cl * Ll + yy * Ww + (f4 - 1) * 4];
            xs4[idx] = v;
        }
    }
    __syncthreads();

    const int v    = tid >> 6;
    const int lofs = tid & 63;
    const int l    = l0 + lofs;
    const int y    = l / Ww;
    const int xp   = l - y * Ww;
    const int thr_base = (y - y0 + 3) * 64 + (xp + 4);

    const float* kb = kgen + (size_t)b * M2 * Ll + (size_t)v * Ll + l;
    const int*   tv = c_tab.v + v * KKt;

    float acc0 = 0.f, acc1 = 0.f, acc2 = 0.f, acc3 = 0.f;

#pragma unroll 7
    for (int kkp = 0; kkp < KKt; kkp++) {
        float kv = kb[(size_t)(kkp * Gg) * Ll];
        int   a  = tv[kkp] + thr_base;
        acc0 = fmaf(kv, xs[a        ], acc0);
        acc1 = fmaf(kv, xs[a + 8192 ], acc1);
        acc2 = fmaf(kv, xs[a + 16384], acc2);
        acc3 = fmaf(kv, xs[a + 24576], acc3);
    }

    float* ob = out + (size_t)b * Cc * Ll + (size_t)((uq * 4) * Gg + v) * Ll + l;
    ob[0 * Gg * Ll] = acc0;
    ob[1 * Gg * Ll] = acc1;
    ob[2 * Gg * Ll] = acc2;
    ob[3 * Gg * Ll] = acc3;
}

// ---------------------------------------------------------------------------
extern "C" void kernel_launch(void* const* d_in, const int* in_sizes, int n_in,
                              void* d_out, int out_size)
{
    const float* x     = (const float*)d_in[0];
    const float* w1    = (const float*)d_in[1];
    const float* gamma = (const float*)d_in[3];
    const float* beta  = (const float*)d_in[4];
    const float* w2    = (const float*)d_in[5];
    const float* b2    = (const float*)d_in[6];

    float* out  = (float*)d_out;
    float* kgen = out + OUT_OFF;

    float* t_ptr = nullptr;
    cudaGetSymbolAddress((void**)&t_ptr, g_t);

    cudaFuncSetAttribute(gemm2_kernel,
                         cudaFuncAttributeMaxDynamicSharedMemorySize, G2_SMEM);
    cudaFuncSetAttribute(involution_kernel,
                         cudaFuncAttributeMaxDynamicSharedMemorySize, 32768 * 4);

    // 1) conv1
    {
        dim3 grid(Ll / 32, 2, Bn);
        gemm1_kernel<<<grid, 256>>>(w1, x, t_ptr);
    }
    // 2) BN batch stats (fp32)
    bn_stats_kernel<<<CrD, 256>>>(gamma, beta);

    // 3) conv2 + fused BN/ReLU (f32x2 packed FMA)
    {
        dim3 grid(Ll / 64, (M2 + 127) / 128, Bn);
        gemm2_kernel<<<grid, 256, G2_SMEM>>>(w2, t_ptr, b2, kgen);
    }
    // 4) involution
    {
        dim3 grid(Ll / 64, 4, Bn);
        involution_kernel<<<grid, 1024, 32768 * 4>>>(x, kgen, out);
    }
}

// round 11
// speedup vs baseline: 1.1589x; 1.0344x over previous
#include <cuda_runtime.h>
#include <math.h>

#define Bn   2
#define Cc   256
#define Hh   56
#define Ww   56
#define Ll   3136
#define CrD  64
#define Gg   16
#define KKt  49
#define M2   784
#define OUT_OFF (Bn*Cc*Ll)

typedef unsigned long long u64t;

// packed f32x2 helpers (sm_103a FFMA2 pipe — fp32-exact)
#define FMA2(d, a, b) \
    asm("fma.rn.f32x2 %0, %1, %2, %0;" : "+l"(d) : "l"(a), "l"(b))
#define DUP2(u, f) \
    asm("mov.b64 %0, {%1, %1};" : "=l"(u) : "r"(__float_as_uint(f)))
__device__ __forceinline__ float lo32(u64t u) { return __uint_as_float((unsigned)(u & 0xffffffffu)); }
__device__ __forceinline__ float hi32(u64t u) { return __uint_as_float((unsigned)(u >> 32)); }

__device__ float g_t[Bn*CrD*Ll];
__device__ float g_scale[CrD];
__device__ float g_shift[CrD];

// tap table: tab[v*49+kkp] = dc*512 + di*64 + dj   (xs layout [ch][8 rows][64 cols])
struct TabT { int v[16 * KKt]; };
__host__ __device__ constexpr TabT make_tab() {
    TabT t{};
    for (int v = 0; v < 16; v++)
        for (int kkp = 0; kkp < KKt; kkp++) {
            int s  = kkp * Gg + v;
            int dc = s / KKt;
            int tp = s - dc * KKt;
            int r7 = tp / 7;
            int di = r7 - 3;
            int dj = tp - r7 * 7 - 3;
            t.v[v * KKt + kkp] = dc * 512 + di * 64 + dj;
        }
    return t;
}
__constant__ TabT c_tab = make_tab();

// ---------------------------------------------------------------------------
// GEMM1: T[b][m][n] = sum_k W1[m][k] * X[b][k][n]   (b1 dropped: BN cancels it)
// M=64, K=256, N=3136. BM=32, BN=32, BK=64. grid (98,2,2)=392. 256 thr.
// micro 2x2 m-packed f32x2.
// ---------------------------------------------------------------------------
#define WP1 36
__global__ __launch_bounds__(256)
void gemm1_kernel(const float* __restrict__ W,
                  const float* __restrict__ X,
                  float* __restrict__ T)
{
    __shared__ float Wm[64 * WP1];   // [k][m]
    __shared__ float As[64 * WP1];   // [k][n]

    int b   = blockIdx.z;
    int bm0 = blockIdx.y * 32;
    int bn0 = blockIdx.x * 32;
    int tid = threadIdx.x;
    int tx  = tid & 15;     // n-pair
    int ty  = tid >> 4;     // m-pair

    const float* Xb = X + (size_t)b * Cc * Ll;
    u64t acc0 = 0ull, acc1 = 0ull;

    for (int k0 = 0; k0 < Cc; k0 += 64) {
#pragma unroll
        for (int i = 0; i < 2; i++) {
            int idx = tid + i * 256;
            int m   = idx >> 4;
            int k4  = idx & 15;
            float4 v = *(const float4*)&W[(size_t)(bm0 + m) * Cc + k0 + k4 * 4];
            Wm[(k4 * 4 + 0) * WP1 + m] = v.x;
            Wm[(k4 * 4 + 1) * WP1 + m] = v.y;
            Wm[(k4 * 4 + 2) * WP1 + m] = v.z;
            Wm[(k4 * 4 + 3) * WP1 + m] = v.w;
        }
#pragma unroll
        for (int i = 0; i < 2; i++) {
            int idx = tid + i * 256;
            int kk  = idx >> 3;
            int n4  = idx & 7;
            float4 v = *(const float4*)&Xb[(size_t)(k0 + kk) * Ll + bn0 + n4 * 4];
            *(float4*)&As[kk * WP1 + n4 * 4] = v;
        }
        __syncthreads();
#pragma unroll 8
        for (int kk = 0; kk < 64; kk++) {
            u64t  w2 = *(const u64t*)&Wm[kk * WP1 + ty * 2];
            float2 a2 = *(const float2*)&As[kk * WP1 + tx * 2];
            u64t an0, an1;
            DUP2(an0, a2.x);
            DUP2(an1, a2.y);
            FMA2(acc0, w2, an0);
            FMA2(acc1, w2, an1);
        }
        __syncthreads();
    }
    {
        int ch0 = bm0 + ty * 2;
        *(float2*)&T[((size_t)b * CrD + ch0) * Ll + bn0 + tx * 2] =
            make_float2(lo32(acc0), lo32(acc1));
        *(float2*)&T[((size_t)b * CrD + ch0 + 1) * Ll + bn0 + tx * 2] =
            make_float2(hi32(acc0), hi32(acc1));
    }
}

// ---------------------------------------------------------------------------
// BN batch stats over g_t -> folded scale/shift. FP32, 512 threads/block.
// ---------------------------------------------------------------------------
__global__ __launch_bounds__(512)
void bn_stats_kernel(const float* __restrict__ gamma,
                     const float* __restrict__ beta)
{
    int ch  = blockIdx.x;
    int tid = threadIdx.x;
    float fs = 0.f, fs2 = 0.f;
    const int F4 = Ll / 4;             // 784 per batch
    for (int i = tid; i < Bn * F4; i += 512) {
        int b  = i / F4;
        int l4 = i - b * F4;
        float4 v = *(const float4*)&g_t[((size_t)b * CrD + ch) * Ll + l4 * 4];
        fs  += v.x + v.y + v.z + v.w;
        fs2 += v.x * v.x + v.y * v.y + v.z * v.z + v.w * v.w;
    }
    __shared__ float sh[512], sh2[512];
    sh[tid] = fs; sh2[tid] = fs2;
    __syncthreads();
    for (int o = 256; o > 0; o >>= 1) {
        if (tid < o) { sh[tid] += sh[tid + o]; sh2[tid] += sh2[tid + o]; }
        __syncthreads();
    }
    if (tid == 0) {
        float n    = (float)(Bn * Ll);
        float mean = sh[0] / n;
        float var  = sh2[0] / n - mean * mean;
        float rstd = rsqrtf(var + 1e-5f);
        float sc   = gamma[ch] * rstd;
        g_scale[ch] = sc;
        g_shift[ch] = beta[ch] - mean * sc;
    }
}

// ---------------------------------------------------------------------------
// GEMM2: Kout = W2 @ relu(bn(T)) + b2.  M=784, K=64 (one stage), N=3136.
// BM=64, BN=64, 256 thr, micro 4x4 (f32x2). Small T_block -> balanced waves.
// grid (49, 13, 2) = 1274 blocks.
// ---------------------------------------------------------------------------
#define WMP 72
#define ASP 68
#define WM_FLOATS (64 * WMP)
#define G2_SMEM ((WM_FLOATS + 64 * ASP) * 4)

extern __shared__ float s_g2[];

__global__ __launch_bounds__(256, 5)
void gemm2_kernel(const float* __restrict__ W2,
                  const float* __restrict__ T,
                  const float* __restrict__ b2,
                  float* __restrict__ Kout)
{
    float* Wm = s_g2;               // [64][72]
    float* As = s_g2 + WM_FLOATS;   // [64][68]

    int b   = blockIdx.z;
    int bm0 = blockIdx.y * 64;
    int bn0 = blockIdx.x * 64;
    int tid = threadIdx.x;
    int tx  = tid & 15;
    int ty  = tid >> 4;

    // W2 tile 64 x 64
#pragma unroll
    for (int i = 0; i < 4; i++) {
        int idx = tid + i * 256;
        int m   = idx >> 4;
        int k4  = idx & 15;
        int gm  = bm0 + m;
        float4 v = make_float4(0.f, 0.f, 0.f, 0.f);
        if (gm < M2)
            v = *(const float4*)&W2[(size_t)gm * CrD + k4 * 4];
        *(float4*)&Wm[m * WMP + k4 * 4] = v;
    }
    // A tile 64 x 64 + fused BN/ReLU
#pragma unroll
    for (int i = 0; i < 4; i++) {
        int idx = tid + i * 256;
        int kk  = idx >> 4;
        int n4  = idx & 15;
        float4 v = *(const float4*)&T[((size_t)b * CrD + kk) * Ll + bn0 + n4 * 4];
        float sc = g_scale[kk], sh = g_shift[kk];
        v.x = fmaxf(fmaf(v.x, sc, sh), 0.f);
        v.y = fmaxf(fmaf(v.y, sc, sh), 0.f);
        v.z = fmaxf(fmaf(v.z, sc, sh), 0.f);
        v.w = fmaxf(fmaf(v.w, sc, sh), 0.f);
        *(float4*)&As[kk * ASP + n4 * 4] = v;
    }
    __syncthreads();

    u64t acc[4][2];
#pragma unroll
    for (int i = 0; i < 4; i++) { acc[i][0] = 0ull; acc[i][1] = 0ull; }

#pragma unroll 4
    for (int k4 = 0; k4 < 16; k4++) {
        u64t a[4][2];
#pragma unroll
        for (int r = 0; r < 4; r++) {
            const float* ap = &As[(k4 * 4 + r) * ASP + tx * 4];
            a[r][0] = *(const u64t*)(ap);
            a[r][1] = *(const u64t*)(ap + 2);
        }
#pragma unroll
        for (int i = 0; i < 4; i++) {
            float4 w = *(const float4*)&Wm[(ty * 4 + i) * WMP + k4 * 4];
            u64t wd;
            DUP2(wd, w.x);
            FMA2(acc[i][0], wd, a[0][0]);
            FMA2(acc[i][1], wd, a[0][1]);
            DUP2(wd, w.y);
            FMA2(acc[i][0], wd, a[1][0]);
            FMA2(acc[i][1], wd, a[1][1]);
            DUP2(wd, w.z);
            FMA2(acc[i][0], wd, a[2][0]);
            FMA2(acc[i][1], wd, a[2][1]);
            DUP2(wd, w.w);
            FMA2(acc[i][0], wd, a[3][0]);
            FMA2(acc[i][1], wd, a[3][1]);
        }
    }

#pragma unroll
    for (int i = 0; i < 4; i++) {
        int gm = bm0 + ty * 4 + i;
        if (gm < M2) {
            float bb = b2[gm];
            float4 v = make_float4(lo32(acc[i][0]) + bb, hi32(acc[i][0]) + bb,
                                   lo32(acc[i][1]) + bb, hi32(acc[i][1]) + bb);
            *(float4*)&Kout[((size_t)b * M2 + gm) * Ll + bn0 + tx * 4] = v;
        }
    }
}

// ---------------------------------------------------------------------------
// Involution, smem-staged x, vectorized staging (unchanged from best).
// ---------------------------------------------------------------------------
extern __shared__ float s_xs[];

__global__ __launch_bounds__(1024, 1)
void involution_kernel(const float* __restrict__ x,
                       const float* __restrict__ kgen,
                       float* __restrict__ out)
{
    float* xs = s_xs;
    float4* xs4 = (float4*)s_xs;

    const int tid = threadIdx.x;
    const int uq  = blockIdx.y;
    const int b   = blockIdx.z;
    const int l0  = blockIdx.x * 64;
    const int y0  = l0 / Ww;

    {
        const float* xb = x + ((size_t)b * Cc + uq * 64) * Ll;
#pragma unroll
        for (int i = 0; i < 8; i++) {
            int idx  = tid + i * 1024;
            int cl   = idx >> 7;
            int rem  = idx & 127;
            int yrel = rem >> 4;
            int f4   = rem & 15;
            int yy   = y0 - 3 + yrel;
            float4 v = make_float4(0.f, 0.f, 0.f, 0.f);
            if (f4 >= 1 && f4 <= 14 && (unsigned)yy < Hh)
                v = *(const float4*)&xb[(size_t)cl * Ll + yy * Ww + (f4 - 1) * 4];
            xs4[idx] = v;
        }
    }
    __syncthreads();

    const int v    = tid >> 6;
    const int lofs = tid & 63;
    const int l    = l0 + lofs;
    const int y    = l / Ww;
    const int xp   = l - y * Ww;
    const int thr_base = (y - y0 + 3) * 64 + (xp + 4);

    const float* kb = kgen + (size_t)b * M2 * Ll + (size_t)v * Ll + l;
    const int*   tv = c_tab.v + v * KKt;

    float acc0 = 0.f, acc1 = 0.f, acc2 = 0.f, acc3 = 0.f;

#pragma unroll 7
    for (int kkp = 0; kkp < KKt; kkp++) {
        float kv = kb[(size_t)(kkp * Gg) * Ll];
        int   a  = tv[kkp] + thr_base;
        acc0 = fmaf(kv, xs[a        ], acc0);
        acc1 = fmaf(kv, xs[a + 8192 ], acc1);
        acc2 = fmaf(kv, xs[a + 16384], acc2);
        acc3 = fmaf(kv, xs[a + 24576], acc3);
    }

    float* ob = out + (size_t)b * Cc * Ll + (size_t)((uq * 4) * Gg + v) * Ll + l;
    ob[0 * Gg * Ll] = acc0;
    ob[1 * Gg * Ll] = acc1;
    ob[2 * Gg * Ll] = acc2;
    ob[3 * Gg * Ll] = acc3;
}

// ---------------------------------------------------------------------------
extern "C" void kernel_launch(void* const* d_in, const int* in_sizes, int n_in,
                              void* d_out, int out_size)
{
    const float* x     = (const float*)d_in[0];
    const float* w1    = (const float*)d_in[1];
    const float* gamma = (const float*)d_in[3];
    const float* beta  = (const float*)d_in[4];
    const float* w2    = (const float*)d_in[5];
    const float* b2    = (const float*)d_in[6];

    float* out  = (float*)d_out;
    float* kgen = out + OUT_OFF;

    float* t_ptr = nullptr;
    cudaGetSymbolAddress((void**)&t_ptr, g_t);

    cudaFuncSetAttribute(gemm2_kernel,
                         cudaFuncAttributeMaxDynamicSharedMemorySize, G2_SMEM);
    cudaFuncSetAttribute(involution_kernel,
                         cudaFuncAttributeMaxDynamicSharedMemorySize, 32768 * 4);

    // 1) conv1
    {
        dim3 grid(Ll / 32, 2, Bn);
        gemm1_kernel<<<grid, 256>>>(w1, x, t_ptr);
    }
    // 2) BN batch stats (fp32, 512 thr)
    bn_stats_kernel<<<CrD, 512>>>(gamma, beta);

    // 3) conv2 + fused BN/ReLU (BM=64/BN=64 tiles, load-balanced)
    {
        dim3 grid(Ll / 64, (M2 + 63) / 64, Bn);
        gemm2_kernel<<<grid, 256, G2_SMEM>>>(w2, t_ptr, b2, kgen);
    }
    // 4) involution
    {
        dim3 grid(Ll / 64, 4, Bn);
        involution_kernel<<<grid, 1024, 32768 * 4>>>(x, kgen, out);
    }
}

// round 12
// speedup vs baseline: 1.1960x; 1.0320x over previous
#include <cuda_runtime.h>
#include <math.h>

#define Bn   2
#define Cc   256
#define Hh   56
#define Ww   56
#define Ll   3136
#define CrD  64
#define Gg   16
#define KKt  49
#define M2   784
#define OUT_OFF (Bn*Cc*Ll)
#define NSLOT 98          // partial-sum slots per channel: 2 b * 49 n-blocks

typedef unsigned long long u64t;

#define FMA2(d, a, b) \
    asm("fma.rn.f32x2 %0, %1, %2, %0;" : "+l"(d) : "l"(a), "l"(b))
#define DUP2(u, f) \
    asm("mov.b64 %0, {%1, %1};" : "=l"(u) : "r"(__float_as_uint(f)))
__device__ __forceinline__ float lo32(u64t u) { return __uint_as_float((unsigned)(u & 0xffffffffu)); }
__device__ __forceinline__ float hi32(u64t u) { return __uint_as_float((unsigned)(u >> 32)); }

__device__ float g_t[Bn*CrD*Ll];
__device__ float g_scale[CrD];
__device__ float g_shift[CrD];
__device__ float g_ps[CrD*NSLOT];   // per-block partial sums
__device__ float g_pq[CrD*NSLOT];   // per-block partial sums of squares

// tap table: tab[v*49+kkp] = dc*512 + di*64 + dj   (xs layout [ch][8 rows][64 cols])
struct TabT { int v[16 * KKt]; };
__host__ __device__ constexpr TabT make_tab() {
    TabT t{};
    for (int v = 0; v < 16; v++)
        for (int kkp = 0; kkp < KKt; kkp++) {
            int s  = kkp * Gg + v;
            int dc = s / KKt;
            int tp = s - dc * KKt;
            int r7 = tp / 7;
            int di = r7 - 3;
            int dj = tp - r7 * 7 - 3;
            t.v[v * KKt + kkp] = dc * 512 + di * 64 + dj;
        }
    return t;
}
__constant__ TabT c_tab = make_tab();

// ---------------------------------------------------------------------------
// GEMM1: T[b][m][n] = sum_k W1[m][k] * X[b][k][n]   (b1 dropped: BN cancels it)
// M=64, K=256, N=3136. Tile 32m x 64n, BK=64, 128 thr, micro 4m x 4n n-packed
// f32x2 (GEMM2's proven inner structure). grid (49, 2, 2) = 196 blocks.
// Epilogue: per-block BN partial sums (sum, sumsq per channel) via shfl.
// ---------------------------------------------------------------------------
#define W1P 68
#define A1P 68
__global__ __launch_bounds__(128)
void gemm1_kernel(const float* __restrict__ W,
                  const float* __restrict__ X,
                  float* __restrict__ T)
{
    __shared__ float Wm[32 * W1P];   // [m][k]
    __shared__ float As[64 * A1P];   // [k][n]

    int b   = blockIdx.z;
    int bm0 = blockIdx.y * 32;
    int bn0 = blockIdx.x * 64;
    int tid = threadIdx.x;
    int tx  = tid & 15;      // 4 n each
    int ty  = tid >> 4;      // 0..7 -> 4 m each

    const float* Xb = X + (size_t)b * Cc * Ll;

    u64t acc[4][2];          // [m][n-half] packed over n-pairs
#pragma unroll
    for (int i = 0; i < 4; i++) { acc[i][0] = 0ull; acc[i][1] = 0ull; }

    for (int k0 = 0; k0 < Cc; k0 += 64) {
        // W tile 32m x 64k (float4 direct copy)
#pragma unroll
        for (int i = 0; i < 4; i++) {
            int idx = tid + i * 128;     // 0..511
            int m   = idx >> 4;
            int k4  = idx & 15;
            float4 v = *(const float4*)&W[(size_t)(bm0 + m) * Cc + k0 + k4 * 4];
            *(float4*)&Wm[m * W1P + k4 * 4] = v;
        }
        // A tile 64k x 64n
#pragma unroll
        for (int i = 0; i < 8; i++) {
            int idx = tid + i * 128;     // 0..1023
            int kk  = idx >> 4;
            int n4  = idx & 15;
            float4 v = *(const float4*)&Xb[(size_t)(k0 + kk) * Ll + bn0 + n4 * 4];
            *(float4*)&As[kk * A1P + n4 * 4] = v;
        }
        __syncthreads();

#pragma unroll 4
        for (int k4 = 0; k4 < 16; k4++) {
            u64t a[4][2];
#pragma unroll
            for (int r = 0; r < 4; r++) {
                const float* ap = &As[(k4 * 4 + r) * A1P + tx * 4];
                a[r][0] = *(const u64t*)(ap);
                a[r][1] = *(const u64t*)(ap + 2);
            }
#pragma unroll
            for (int i = 0; i < 4; i++) {
                float4 w = *(const float4*)&Wm[(ty * 4 + i) * W1P + k4 * 4];
                u64t wd;
                DUP2(wd, w.x);
                FMA2(acc[i][0], wd, a[0][0]);
                FMA2(acc[i][1], wd, a[0][1]);
                DUP2(wd, w.y);
                FMA2(acc[i][0], wd, a[1][0]);
                FMA2(acc[i][1], wd, a[1][1]);
                DUP2(wd, w.z);
                FMA2(acc[i][0], wd, a[2][0]);
                FMA2(acc[i][1], wd, a[2][1]);
                DUP2(wd, w.w);
                FMA2(acc[i][0], wd, a[3][0]);
                FMA2(acc[i][1], wd, a[3][1]);
            }
        }
        __syncthreads();
    }

    // store T + per-channel partial sums
#pragma unroll
    for (int i = 0; i < 4; i++) {
        int ch = bm0 + ty * 4 + i;
        float4 v = make_float4(lo32(acc[i][0]), hi32(acc[i][0]),
                               lo32(acc[i][1]), hi32(acc[i][1]));
        *(float4*)&T[((size_t)b * CrD + ch) * Ll + bn0 + tx * 4] = v;

        float s = v.x + v.y + v.z + v.w;
        float q = v.x * v.x + v.y * v.y + v.z * v.z + v.w * v.w;
#pragma unroll
        for (int o = 8; o > 0; o >>= 1) {
            s += __shfl_xor_sync(0xffffffffu, s, o);
            q += __shfl_xor_sync(0xffffffffu, q, o);
        }
        if (tx == 0) {
            int slot = b * 49 + blockIdx.x;
            g_ps[ch * NSLOT + slot] = s;
            g_pq[ch * NSLOT + slot] = q;
        }
    }
}

// ---------------------------------------------------------------------------
// BN finalize: reduce 98 partials per channel -> folded scale/shift. 1 block.
// ---------------------------------------------------------------------------
__global__ __launch_bounds__(256)
void bn_finalize_kernel(const float* __restrict__ gamma,
                        const float* __restrict__ beta)
{
    __shared__ float shS[256], shQ[256];
    int tid  = threadIdx.x;
    int ch   = tid & 63;
    int part = tid >> 6;     // 0..3
    float s = 0.f, q = 0.f;
    for (int i = part; i < NSLOT; i += 4) {
        s += g_ps[ch * NSLOT + i];
        q += g_pq[ch * NSLOT + i];
    }
    shS[part * 64 + ch] = s;
    shQ[part * 64 + ch] = q;
    __syncthreads();
    if (tid < 64) {
        float S = shS[tid] + shS[64 + tid] + shS[128 + tid] + shS[192 + tid];
        float Q = shQ[tid] + shQ[64 + tid] + shQ[128 + tid] + shQ[192 + tid];
        float n    = (float)(Bn * Ll);
        float mean = S / n;
        float var  = Q / n - mean * mean;
        float rstd = rsqrtf(var + 1e-5f);
        float sc   = gamma[tid] * rstd;
        g_scale[tid] = sc;
        g_shift[tid] = beta[tid] - mean * sc;
    }
}

// ---------------------------------------------------------------------------
// GEMM2: Kout = W2 @ relu(bn(T)) + b2.  M=784, K=64 (one stage), N=3136.
// BM=64, BN=64, 256 thr, micro 4x4 (f32x2). grid (49, 13, 2) = 1274 blocks.
// ---------------------------------------------------------------------------
#define WMP 72
#define ASP 68
#define WM_FLOATS (64 * WMP)
#define G2_SMEM ((WM_FLOATS + 64 * ASP) * 4)

extern __shared__ float s_g2[];

__global__ __launch_bounds__(256, 5)
void gemm2_kernel(const float* __restrict__ W2,
                  const float* __restrict__ T,
                  const float* __restrict__ b2,
                  float* __restrict__ Kout)
{
    float* Wm = s_g2;               // [64][72]
    float* As = s_g2 + WM_FLOATS;   // [64][68]

    int b   = blockIdx.z;
    int bm0 = blockIdx.y * 64;
    int bn0 = blockIdx.x * 64;
    int tid = threadIdx.x;
    int tx  = tid & 15;
    int ty  = tid >> 4;

#pragma unroll
    for (int i = 0; i < 4; i++) {
        int idx = tid + i * 256;
        int m   = idx >> 4;
        int k4  = idx & 15;
        int gm  = bm0 + m;
        float4 v = make_float4(0.f, 0.f, 0.f, 0.f);
        if (gm < M2)
            v = *(const float4*)&W2[(size_t)gm * CrD + k4 * 4];
        *(float4*)&Wm[m * WMP + k4 * 4] = v;
    }
#pragma unroll
    for (int i = 0; i < 4; i++) {
        int idx = tid + i * 256;
        int kk  = idx >> 4;
        int n4  = idx & 15;
        float4 v = *(const float4*)&T[((size_t)b * CrD + kk) * Ll + bn0 + n4 * 4];
        float sc = g_scale[kk], sh = g_shift[kk];
        v.x = fmaxf(fmaf(v.x, sc, sh), 0.f);
        v.y = fmaxf(fmaf(v.y, sc, sh), 0.f);
        v.z = fmaxf(fmaf(v.z, sc, sh), 0.f);
        v.w = fmaxf(fmaf(v.w, sc, sh), 0.f);
        *(float4*)&As[kk * ASP + n4 * 4] = v;
    }
    __syncthreads();

    u64t acc[4][2];
#pragma unroll
    for (int i = 0; i < 4; i++) { acc[i][0] = 0ull; acc[i][1] = 0ull; }

#pragma unroll 4
    for (int k4 = 0; k4 < 16; k4++) {
        u64t a[4][2];
#pragma unroll
        for (int r = 0; r < 4; r++) {
            const float* ap = &As[(k4 * 4 + r) * ASP + tx * 4];
            a[r][0] = *(const u64t*)(ap);
            a[r][1] = *(const u64t*)(ap + 2);
        }
#pragma unroll
        for (int i = 0; i < 4; i++) {
            float4 w = *(const float4*)&Wm[(ty * 4 + i) * WMP + k4 * 4];
            u64t wd;
            DUP2(wd, w.x);
            FMA2(acc[i][0], wd, a[0][0]);
            FMA2(acc[i][1], wd, a[0][1]);
            DUP2(wd, w.y);
            FMA2(acc[i][0], wd, a[1][0]);
            FMA2(acc[i][1], wd, a[1][1]);
            DUP2(wd, w.z);
            FMA2(acc[i][0], wd, a[2][0]);
            FMA2(acc[i][1], wd, a[2][1]);
            DUP2(wd, w.w);
            FMA2(acc[i][0], wd, a[3][0]);
            FMA2(acc[i][1], wd, a[3][1]);
        }
    }

#pragma unroll
    for (int i = 0; i < 4; i++) {
        int gm = bm0 + ty * 4 + i;
        if (gm < M2) {
            float bb = b2[gm];
            float4 v = make_float4(lo32(acc[i][0]) + bb, hi32(acc[i][0]) + bb,
                                   lo32(acc[i][1]) + bb, hi32(acc[i][1]) + bb);
            *(float4*)&Kout[((size_t)b * M2 + gm) * Ll + bn0 + tx * 4] = v;
        }
    }
}

// ---------------------------------------------------------------------------
// Involution, smem-staged x, vectorized staging (unchanged from best).
// ---------------------------------------------------------------------------
extern __shared__ float s_xs[];

__global__ __launch_bounds__(1024, 1)
void involution_kernel(const float* __restrict__ x,
                       const float* __restrict__ kgen,
                       float* __restrict__ out)
{
    float* xs = s_xs;
    float4* xs4 = (float4*)s_xs;

    const int tid = threadIdx.x;
    const int uq  = blockIdx.y;
    const int b   = blockIdx.z;
    const int l0  = blockIdx.x * 64;
    const int y0  = l0 / Ww;

    {
        const float* xb = x + ((size_t)b * Cc + uq * 64) * Ll;
#pragma unroll
        for (int i = 0; i < 8; i++) {
            int idx  = tid + i * 1024;
            int cl   = idx >> 7;
            int rem  = idx & 127;
            int yrel = rem >> 4;
            int f4   = rem & 15;
            int yy   = y0 - 3 + yrel;
            float4 v = make_float4(0.f, 0.f, 0.f, 0.f);
            if (f4 >= 1 && f4 <= 14 && (unsigned)yy < Hh)
                v = *(const float4*)&xb[(size_t)cl * Ll + yy * Ww + (f4 - 1) * 4];
            xs4[idx] = v;
        }
    }
    __syncthreads();

    const int v    = tid >> 6;
    const int lofs = tid & 63;
    const int l    = l0 + lofs;
    const int y    = l / Ww;
    const int xp   = l - y * Ww;
    const int thr_base = (y - y0 + 3) * 64 + (xp + 4);

    const float* kb = kgen + (size_t)b * M2 * Ll + (size_t)v * Ll + l;
    const int*   tv = c_tab.v + v * KKt;

    float acc0 = 0.f, acc1 = 0.f, acc2 = 0.f, acc3 = 0.f;

#pragma unroll 7
    for (int kkp = 0; kkp < KKt; kkp++) {
        float kv = kb[(size_t)(kkp * Gg) * Ll];
        int   a  = tv[kkp] + thr_base;
        acc0 = fmaf(kv, xs[a        ], acc0);
        acc1 = fmaf(kv, xs[a + 8192 ], acc1);
        acc2 = fmaf(kv, xs[a + 16384], acc2);
        acc3 = fmaf(kv, xs[a + 24576], acc3);
    }

    float* ob = out + (size_t)b * Cc * Ll + (size_t)((uq * 4) * Gg + v) * Ll + l;
    ob[0 * Gg * Ll] = acc0;
    ob[1 * Gg * Ll] = acc1;
    ob[2 * Gg * Ll] = acc2;
    ob[3 * Gg * Ll] = acc3;
}

// ---------------------------------------------------------------------------
extern "C" void kernel_launch(void* const* d_in, const int* in_sizes, int n_in,
                              void* d_out, int out_size)
{
    const float* x     = (const float*)d_in[0];
    const float* w1    = (const float*)d_in[1];
    const float* gamma = (const float*)d_in[3];
    const float* beta  = (const float*)d_in[4];
    const float* w2    = (const float*)d_in[5];
    const float* b2    = (const float*)d_in[6];

    float* out  = (float*)d_out;
    float* kgen = out + OUT_OFF;

    float* t_ptr = nullptr;
    cudaGetSymbolAddress((void**)&t_ptr, g_t);

    cudaFuncSetAttribute(gemm2_kernel,
                         cudaFuncAttributeMaxDynamicSharedMemorySize, G2_SMEM);
    cudaFuncSetAttribute(involution_kernel,
                         cudaFuncAttributeMaxDynamicSharedMemorySize, 32768 * 4);

    // 1) conv1 + fused BN partial sums
    {
        dim3 grid(Ll / 64, 2, Bn);
        gemm1_kernel<<<grid, 128>>>(w1, x, t_ptr);
    }
    // 2) BN finalize (tiny)
    bn_finalize_kernel<<<1, 256>>>(gamma, beta);

    // 3) conv2 + fused BN/ReLU
    {
        dim3 grid(Ll / 64, (M2 + 63) / 64, Bn);
        gemm2_kernel<<<grid, 256, G2_SMEM>>>(w2, t_ptr, b2, kgen);
    }
    // 4) involution
    {
        dim3 grid(Ll / 64, 4, Bn);
        involution_kernel<<<grid, 1024, 32768 * 4>>>(x, kgen, out);
    }
}

// round 13
// speedup vs baseline: 1.2407x; 1.0373x over previous
#include <cuda_runtime.h>
#include <math.h>

#define Bn   2
#define Cc   256
#define Hh   56
#define Ww   56
#define Ll   3136
#define CrD  64
#define Gg   16
#define KKt  49
#define M2   784
#define OUT_OFF (Bn*Cc*Ll)
#define NSLOT 98          // partial-sum slots per channel: 2 b * 49 n-blocks

typedef unsigned long long u64t;

#define FMA2(d, a, b) \
    asm("fma.rn.f32x2 %0, %1, %2, %0;" : "+l"(d) : "l"(a), "l"(b))
#define DUP2(u, f) \
    asm("mov.b64 %0, {%1, %1};" : "=l"(u) : "r"(__float_as_uint(f)))
__device__ __forceinline__ float lo32(u64t u) { return __uint_as_float((unsigned)(u & 0xffffffffu)); }
__device__ __forceinline__ float hi32(u64t u) { return __uint_as_float((unsigned)(u >> 32)); }

__device__ float g_t[Bn*CrD*Ll];
__device__ float g_scale[CrD];
__device__ float g_shift[CrD];
__device__ float g_ps[CrD*NSLOT];
__device__ float g_pq[CrD*NSLOT];

// tap table: tab[v*49+kkp] = dc*512 + di*64 + dj   (xs layout [ch][8 rows][64 cols])
struct TabT { int v[16 * KKt]; };
__host__ __device__ constexpr TabT make_tab() {
    TabT t{};
    for (int v = 0; v < 16; v++)
        for (int kkp = 0; kkp < KKt; kkp++) {
            int s  = kkp * Gg + v;
            int dc = s / KKt;
            int tp = s - dc * KKt;
            int r7 = tp / 7;
            int di = r7 - 3;
            int dj = tp - r7 * 7 - 3;
            t.v[v * KKt + kkp] = dc * 512 + di * 64 + dj;
        }
    return t;
}
__constant__ TabT c_tab = make_tab();

// ---------------------------------------------------------------------------
// GEMM1 + BN partial sums (identical compute to R11 winner).
// ---------------------------------------------------------------------------
#define W1P 68
#define A1P 68
__global__ __launch_bounds__(128)
void gemm1_kernel(const float* __restrict__ W,
                  const float* __restrict__ X,
                  float* __restrict__ T)
{
    __shared__ float Wm[32 * W1P];
    __shared__ float As[64 * A1P];

    int b   = blockIdx.z;
    int bm0 = blockIdx.y * 32;
    int bn0 = blockIdx.x * 64;
    int tid = threadIdx.x;
    int tx  = tid & 15;
    int ty  = tid >> 4;

    if (tid == 0) cudaTriggerProgrammaticLaunchCompletion();

    const float* Xb = X + (size_t)b * Cc * Ll;

    u64t acc[4][2];
#pragma unroll
    for (int i = 0; i < 4; i++) { acc[i][0] = 0ull; acc[i][1] = 0ull; }

    for (int k0 = 0; k0 < Cc; k0 += 64) {
#pragma unroll
        for (int i = 0; i < 4; i++) {
            int idx = tid + i * 128;
            int m   = idx >> 4;
            int k4  = idx & 15;
            float4 v = *(const float4*)&W[(size_t)(bm0 + m) * Cc + k0 + k4 * 4];
            *(float4*)&Wm[m * W1P + k4 * 4] = v;
        }
#pragma unroll
        for (int i = 0; i < 8; i++) {
            int idx = tid + i * 128;
            int kk  = idx >> 4;
            int n4  = idx & 15;
            float4 v = *(const float4*)&Xb[(size_t)(k0 + kk) * Ll + bn0 + n4 * 4];
            *(float4*)&As[kk * A1P + n4 * 4] = v;
        }
        __syncthreads();

#pragma unroll 4
        for (int k4 = 0; k4 < 16; k4++) {
            u64t a[4][2];
#pragma unroll
            for (int r = 0; r < 4; r++) {
                const float* ap = &As[(k4 * 4 + r) * A1P + tx * 4];
                a[r][0] = *(const u64t*)(ap);
                a[r][1] = *(const u64t*)(ap + 2);
            }
#pragma unroll
            for (int i = 0; i < 4; i++) {
                float4 w = *(const float4*)&Wm[(ty * 4 + i) * W1P + k4 * 4];
                u64t wd;
                DUP2(wd, w.x);
                FMA2(acc[i][0], wd, a[0][0]);
                FMA2(acc[i][1], wd, a[0][1]);
                DUP2(wd, w.y);
                FMA2(acc[i][0], wd, a[1][0]);
                FMA2(acc[i][1], wd, a[1][1]);
                DUP2(wd, w.z);
                FMA2(acc[i][0], wd, a[2][0]);
                FMA2(acc[i][1], wd, a[2][1]);
                DUP2(wd, w.w);
                FMA2(acc[i][0], wd, a[3][0]);
                FMA2(acc[i][1], wd, a[3][1]);
            }
        }
        __syncthreads();
    }

#pragma unroll
    for (int i = 0; i < 4; i++) {
        int ch = bm0 + ty * 4 + i;
        float4 v = make_float4(lo32(acc[i][0]), hi32(acc[i][0]),
                               lo32(acc[i][1]), hi32(acc[i][1]));
        *(float4*)&T[((size_t)b * CrD + ch) * Ll + bn0 + tx * 4] = v;

        float s = v.x + v.y + v.z + v.w;
        float q = v.x * v.x + v.y * v.y + v.z * v.z + v.w * v.w;
#pragma unroll
        for (int o = 8; o > 0; o >>= 1) {
            s += __shfl_xor_sync(0xffffffffu, s, o);
            q += __shfl_xor_sync(0xffffffffu, q, o);
        }
        if (tx == 0) {
            int slot = b * 49 + blockIdx.x;
            g_ps[ch * NSLOT + slot] = s;
            g_pq[ch * NSLOT + slot] = q;
        }
    }
}

// ---------------------------------------------------------------------------
// BN finalize (PDL: sync before reading partials).
// ---------------------------------------------------------------------------
__global__ __launch_bounds__(256)
void bn_finalize_kernel(const float* __restrict__ gamma,
                        const float* __restrict__ beta)
{
    __shared__ float shS[256], shQ[256];
    int tid  = threadIdx.x;
    int ch   = tid & 63;
    int part = tid >> 6;
    float gm = (tid < 64) ? gamma[tid] : 0.f;   // independent input loads
    float bt = (tid < 64) ? beta[tid]  : 0.f;
    if (tid == 0) cudaTriggerProgrammaticLaunchCompletion();

    cudaGridDependencySynchronize();            // wait for gemm1 partials

    float s = 0.f, q = 0.f;
    for (int i = part; i < NSLOT; i += 4) {
        s += g_ps[ch * NSLOT + i];
        q += g_pq[ch * NSLOT + i];
    }
    shS[part * 64 + ch] = s;
    shQ[part * 64 + ch] = q;
    __syncthreads();
    if (tid < 64) {
        float S = shS[tid] + shS[64 + tid] + shS[128 + tid] + shS[192 + tid];
        float Q = shQ[tid] + shQ[64 + tid] + shQ[128 + tid] + shQ[192 + tid];
        float n    = (float)(Bn * Ll);
        float mean = S / n;
        float var  = Q / n - mean * mean;
        float rstd = rsqrtf(var + 1e-5f);
        float sc   = gm * rstd;
        g_scale[tid] = sc;
        g_shift[tid] = bt - mean * sc;
    }
}

// ---------------------------------------------------------------------------
// GEMM2 (PDL: W2 tile loaded before the dependency sync).
// ---------------------------------------------------------------------------
#define WMP 72
#define ASP 68
#define WM_FLOATS (64 * WMP)
#define G2_SMEM ((WM_FLOATS + 64 * ASP) * 4)

extern __shared__ float s_g2[];

__global__ __launch_bounds__(256, 5)
void gemm2_kernel(const float* __restrict__ W2,
                  const float* __restrict__ T,
                  const float* __restrict__ b2,
                  float* __restrict__ Kout)
{
    float* Wm = s_g2;
    float* As = s_g2 + WM_FLOATS;

    int b   = blockIdx.z;
    int bm0 = blockIdx.y * 64;
    int bn0 = blockIdx.x * 64;
    int tid = threadIdx.x;
    int tx  = tid & 15;
    int ty  = tid >> 4;

    // independent prologue: W2 tile
#pragma unroll
    for (int i = 0; i < 4; i++) {
        int idx = tid + i * 256;
        int m   = idx >> 4;
        int k4  = idx & 15;
        int gm  = bm0 + m;
        float4 v = make_float4(0.f, 0.f, 0.f, 0.f);
        if (gm < M2)
            v = *(const float4*)&W2[(size_t)gm * CrD + k4 * 4];
        *(float4*)&Wm[m * WMP + k4 * 4] = v;
    }
    if (tid == 0) cudaTriggerProgrammaticLaunchCompletion();

    cudaGridDependencySynchronize();    // wait for gemm1 (T) + finalize (scale)

#pragma unroll
    for (int i = 0; i < 4; i++) {
        int idx = tid + i * 256;
        int kk  = idx >> 4;
        int n4  = idx & 15;
        float4 v = *(const float4*)&T[((size_t)b * CrD + kk) * Ll + bn0 + n4 * 4];
        float sc = g_scale[kk], sh = g_shift[kk];
        v.x = fmaxf(fmaf(v.x, sc, sh), 0.f);
        v.y = fmaxf(fmaf(v.y, sc, sh), 0.f);
        v.z = fmaxf(fmaf(v.z, sc, sh), 0.f);
        v.w = fmaxf(fmaf(v.w, sc, sh), 0.f);
        *(float4*)&As[kk * ASP + n4 * 4] = v;
    }
    __syncthreads();

    u64t acc[4][2];
#pragma unroll
    for (int i = 0; i < 4; i++) { acc[i][0] = 0ull; acc[i][1] = 0ull; }

#pragma unroll 4
    for (int k4 = 0; k4 < 16; k4++) {
        u64t a[4][2];
#pragma unroll
        for (int r = 0; r < 4; r++) {
            const float* ap = &As[(k4 * 4 + r) * ASP + tx * 4];
            a[r][0] = *(const u64t*)(ap);
            a[r][1] = *(const u64t*)(ap + 2);
        }
#pragma unroll
        for (int i = 0; i < 4; i++) {
            float4 w = *(const float4*)&Wm[(ty * 4 + i) * WMP + k4 * 4];
            u64t wd;
            DUP2(wd, w.x);
            FMA2(acc[i][0], wd, a[0][0]);
            FMA2(acc[i][1], wd, a[0][1]);
            DUP2(wd, w.y);
            FMA2(acc[i][0], wd, a[1][0]);
            FMA2(acc[i][1], wd, a[1][1]);
            DUP2(wd, w.z);
            FMA2(acc[i][0], wd, a[2][0]);
            FMA2(acc[i][1], wd, a[2][1]);
            DUP2(wd, w.w);
            FMA2(acc[i][0], wd, a[3][0]);
            FMA2(acc[i][1], wd, a[3][1]);
        }
    }

#pragma unroll
    for (int i = 0; i < 4; i++) {
        int gm = bm0 + ty * 4 + i;
        if (gm < M2) {
            float bb = b2[gm];
            float4 v = make_float4(lo32(acc[i][0]) + bb, hi32(acc[i][0]) + bb,
                                   lo32(acc[i][1]) + bb, hi32(acc[i][1]) + bb);
            *(float4*)&Kout[((size_t)b * M2 + gm) * Ll + bn0 + tx * 4] = v;
        }
    }
}

// ---------------------------------------------------------------------------
// Involution (PDL: full x staging before the dependency sync).
// ---------------------------------------------------------------------------
extern __shared__ float s_xs[];

__global__ __launch_bounds__(1024, 1)
void involution_kernel(const float* __restrict__ x,
                       const float* __restrict__ kgen,
                       float* __restrict__ out)
{
    float* xs = s_xs;
    float4* xs4 = (float4*)s_xs;

    const int tid = threadIdx.x;
    const int uq  = blockIdx.y;
    const int b   = blockIdx.z;
    const int l0  = blockIdx.x * 64;
    const int y0  = l0 / Ww;

    // independent prologue: stage x tile (input only)
    {
        const float* xb = x + ((size_t)b * Cc + uq * 64) * Ll;
#pragma unroll
        for (int i = 0; i < 8; i++) {
            int idx  = tid + i * 1024;
            int cl   = idx >> 7;
            int rem  = idx & 127;
            int yrel = rem >> 4;
            int f4   = rem & 15;
            int yy   = y0 - 3 + yrel;
            float4 v = make_float4(0.f, 0.f, 0.f, 0.f);
            if (f4 >= 1 && f4 <= 14 && (unsigned)yy < Hh)
                v = *(const float4*)&xb[(size_t)cl * Ll + yy * Ww + (f4 - 1) * 4];
            xs4[idx] = v;
        }
    }
    if (tid == 0) cudaTriggerProgrammaticLaunchCompletion();
    __syncthreads();

    cudaGridDependencySynchronize();    // wait for gemm2 (kgen)

    const int v    = tid >> 6;
    const int lofs = tid & 63;
    const int l    = l0 + lofs;
    const int y    = l / Ww;
    const int xp   = l - y * Ww;
    const int thr_base = (y - y0 + 3) * 64 + (xp + 4);

    const float* kb = kgen + (size_t)b * M2 * Ll + (size_t)v * Ll + l;
    const int*   tv = c_tab.v + v * KKt;

    float acc0 = 0.f, acc1 = 0.f, acc2 = 0.f, acc3 = 0.f;

#pragma unroll 7
    for (int kkp = 0; kkp < KKt; kkp++) {
        float kv = kb[(size_t)(kkp * Gg) * Ll];
        int   a  = tv[kkp] + thr_base;
        acc0 = fmaf(kv, xs[a        ], acc0);
        acc1 = fmaf(kv, xs[a + 8192 ], acc1);
        acc2 = fmaf(kv, xs[a + 16384], acc2);
        acc3 = fmaf(kv, xs[a + 24576], acc3);
    }

    float* ob = out + (size_t)b * Cc * Ll + (size_t)((uq * 4) * Gg + v) * Ll + l;
    ob[0 * Gg * Ll] = acc0;
    ob[1 * Gg * Ll] = acc1;
    ob[2 * Gg * Ll] = acc2;
    ob[3 * Gg * Ll] = acc3;
}

// ---------------------------------------------------------------------------
static void launch_pdl(const void* fn, dim3 grid, dim3 block, size_t smem,
                       void** args)
{
    cudaLaunchConfig_t cfg = {};
    cfg.gridDim = grid;
    cfg.blockDim = block;
    cfg.dynamicSmemBytes = smem;
    cfg.stream = 0;
    cudaLaunchAttribute attr;
    attr.id = cudaLaunchAttributeProgrammaticStreamSerialization;
    attr.val.programmaticStreamSerializationAllowed = 1;
    cfg.attrs = &attr;
    cfg.numAttrs = 1;
    cudaLaunchKernelExC(&cfg, fn, args);
}

extern "C" void kernel_launch(void* const* d_in, const int* in_sizes, int n_in,
                              void* d_out, int out_size)
{
    const float* x     = (const float*)d_in[0];
    const float* w1    = (const float*)d_in[1];
    const float* gamma = (const float*)d_in[3];
    const float* beta  = (const float*)d_in[4];
    const float* w2    = (const float*)d_in[5];
    const float* b2    = (const float*)d_in[6];

    float* out  = (float*)d_out;
    float* kgen = out + OUT_OFF;

    float* t_ptr = nullptr;
    cudaGetSymbolAddress((void**)&t_ptr, g_t);

    cudaFuncSetAttribute(gemm2_kernel,
                         cudaFuncAttributeMaxDynamicSharedMemorySize, G2_SMEM);
    cudaFuncSetAttribute(involution_kernel,
                         cudaFuncAttributeMaxDynamicSharedMemorySize, 32768 * 4);

    // 1) conv1 + BN partial sums
    {
        dim3 grid(Ll / 64, 2, Bn);
        gemm1_kernel<<<grid, 128>>>(w1, x, t_ptr);
    }
    // 2) BN finalize (PDL)
    {
        void* args[] = {(void*)&gamma, (void*)&beta};
        launch_pdl((const void*)bn_finalize_kernel, dim3(1, 1, 1),
                   dim3(256, 1, 1), 0, args);
    }
    // 3) conv2 + fused BN/ReLU (PDL: W2 prologue overlaps)
    {
        void* args[] = {(void*)&w2, (void*)&t_ptr, (void*)&b2, (void*)&kgen};
        launch_pdl((const void*)gemm2_kernel,
                   dim3(Ll / 64, (M2 + 63) / 64, Bn),
                   dim3(256, 1, 1), G2_SMEM, args);
    }
    // 4) involution (PDL: x staging overlaps gemm2 tail)
    {
        void* args[] = {(void*)&x, (void*)&kgen, (void*)&out};
        launch_pdl((const void*)involution_kernel,
                   dim3(Ll / 64, 4, Bn),
                   dim3(1024, 1, 1), 32768 * 4, args);
    }
}

// round 17
// speedup vs baseline: 1.2867x; 1.0371x over previous
#include <cuda_runtime.h>
#include <math.h>

#define Bn   2
#define Cc   256
#define Hh   56
#define Ww   56
#define Ll   3136
#define CrD  64
#define Gg   16
#define KKt  49
#define M2   784
#define OUT_OFF (Bn*Cc*Ll)
#define NSLOT 98          // partial-sum slots per channel: 2 b * 49 n-blocks

typedef unsigned long long u64t;

#define FMA2(d, a, b) \
    asm("fma.rn.f32x2 %0, %1, %2, %0;" : "+l"(d) : "l"(a), "l"(b))
#define DUP2(u, f) \
    asm("mov.b64 %0, {%1, %1};" : "=l"(u) : "r"(__float_as_uint(f)))
__device__ __forceinline__ float lo32(u64t u) { return __uint_as_float((unsigned)(u & 0xffffffffu)); }
__device__ __forceinline__ float hi32(u64t u) { return __uint_as_float((unsigned)(u >> 32)); }

__device__ float g_t[Bn*CrD*Ll];
__device__ float g_scale[CrD];
__device__ float g_shift[CrD];
__device__ float g_ps[CrD*NSLOT];
__device__ float g_pq[CrD*NSLOT];

// tap table: tab[v*49+kkp] = dc*512 + di*64 + dj   (xs layout [ch][8 rows][64 cols])
struct TabT { int v[16 * KKt]; };
__host__ __device__ constexpr TabT make_tab() {
    TabT t{};
    for (int v = 0; v < 16; v++)
        for (int kkp = 0; kkp < KKt; kkp++) {
            int s  = kkp * Gg + v;
            int dc = s / KKt;
            int tp = s - dc * KKt;
            int r7 = tp / 7;
            int di = r7 - 3;
            int dj = tp - r7 * 7 - 3;
            t.v[v * KKt + kkp] = dc * 512 + di * 64 + dj;
        }
    return t;
}
__constant__ TabT c_tab = make_tab();

// ---------------------------------------------------------------------------
// GEMM1 + BN partial sums (R12 winner, unchanged).
// ---------------------------------------------------------------------------
#define W1P 68
#define A1P 68
__global__ __launch_bounds__(128)
void gemm1_kernel(const float* __restrict__ W,
                  const float* __restrict__ X,
                  float* __restrict__ T)
{
    __shared__ float Wm[32 * W1P];
    __shared__ float As[64 * A1P];

    int b   = blockIdx.z;
    int bm0 = blockIdx.y * 32;
    int bn0 = blockIdx.x * 64;
    int tid = threadIdx.x;
    int tx  = tid & 15;
    int ty  = tid >> 4;

    if (tid == 0) cudaTriggerProgrammaticLaunchCompletion();

    const float* Xb = X + (size_t)b * Cc * Ll;

    u64t acc[4][2];
#pragma unroll
    for (int i = 0; i < 4; i++) { acc[i][0] = 0ull; acc[i][1] = 0ull; }

    for (int k0 = 0; k0 < Cc; k0 += 64) {
#pragma unroll
        for (int i = 0; i < 4; i++) {
            int idx = tid + i * 128;
            int m   = idx >> 4;
            int k4  = idx & 15;
            float4 v = *(const float4*)&W[(size_t)(bm0 + m) * Cc + k0 + k4 * 4];
            *(float4*)&Wm[m * W1P + k4 * 4] = v;
        }
#pragma unroll
        for (int i = 0; i < 8; i++) {
            int idx = tid + i * 128;
            int kk  = idx >> 4;
            int n4  = idx & 15;
            float4 v = *(const float4*)&Xb[(size_t)(k0 + kk) * Ll + bn0 + n4 * 4];
            *(float4*)&As[kk * A1P + n4 * 4] = v;
        }
        __syncthreads();

#pragma unroll 4
        for (int k4 = 0; k4 < 16; k4++) {
            u64t a[4][2];
#pragma unroll
            for (int r = 0; r < 4; r++) {
                const float* ap = &As[(k4 * 4 + r) * A1P + tx * 4];
                a[r][0] = *(const u64t*)(ap);
                a[r][1] = *(const u64t*)(ap + 2);
            }
#pragma unroll
            for (int i = 0; i < 4; i++) {
                float4 w = *(const float4*)&Wm[(ty * 4 + i) * W1P + k4 * 4];
                u64t wd;
                DUP2(wd, w.x);
                FMA2(acc[i][0], wd, a[0][0]);
                FMA2(acc[i][1], wd, a[0][1]);
                DUP2(wd, w.y);
                FMA2(acc[i][0], wd, a[1][0]);
                FMA2(acc[i][1], wd, a[1][1]);
                DUP2(wd, w.z);
                FMA2(acc[i][0], wd, a[2][0]);
                FMA2(acc[i][1], wd, a[2][1]);
                DUP2(wd, w.w);
                FMA2(acc[i][0], wd, a[3][0]);
                FMA2(acc[i][1], wd, a[3][1]);
            }
        }
        __syncthreads();
    }

#pragma unroll
    for (int i = 0; i < 4; i++) {
        int ch = bm0 + ty * 4 + i;
        float4 v = make_float4(lo32(acc[i][0]), hi32(acc[i][0]),
                               lo32(acc[i][1]), hi32(acc[i][1]));
        *(float4*)&T[((size_t)b * CrD + ch) * Ll + bn0 + tx * 4] = v;

        float s = v.x + v.y + v.z + v.w;
        float q = v.x * v.x + v.y * v.y + v.z * v.z + v.w * v.w;
#pragma unroll
        for (int o = 8; o > 0; o >>= 1) {
            s += __shfl_xor_sync(0xffffffffu, s, o);
            q += __shfl_xor_sync(0xffffffffu, q, o);
        }
        if (tx == 0) {
            int slot = b * 49 + blockIdx.x;
            g_ps[ch * NSLOT + slot] = s;
            g_pq[ch * NSLOT + slot] = q;
        }
    }
}

// ---------------------------------------------------------------------------
// BN finalize (PDL, unchanged).
// ---------------------------------------------------------------------------
__global__ __launch_bounds__(256)
void bn_finalize_kernel(const float* __restrict__ gamma,
                        const float* __restrict__ beta)
{
    __shared__ float shS[256], shQ[256];
    int tid  = threadIdx.x;
    int ch   = tid & 63;
    int part = tid >> 6;
    float gm = (tid < 64) ? gamma[tid] : 0.f;
    float bt = (tid < 64) ? beta[tid]  : 0.f;
    if (tid == 0) cudaTriggerProgrammaticLaunchCompletion();

    cudaGridDependencySynchronize();

    float s = 0.f, q = 0.f;
    for (int i = part; i < NSLOT; i += 4) {
        s += g_ps[ch * NSLOT + i];
        q += g_pq[ch * NSLOT + i];
    }
    shS[part * 64 + ch] = s;
    shQ[part * 64 + ch] = q;
    __syncthreads();
    if (tid < 64) {
        float S = shS[tid] + shS[64 + tid] + shS[128 + tid] + shS[192 + tid];
        float Q = shQ[tid] + shQ[64 + tid] + shQ[128 + tid] + shQ[192 + tid];
        float n    = (float)(Bn * Ll);
        float mean = S / n;
        float var  = Q / n - mean * mean;
        float rstd = rsqrtf(var + 1e-5f);
        float sc   = gm * rstd;
        g_scale[tid] = sc;
        g_shift[tid] = bt - mean * sc;
    }
}

// ---------------------------------------------------------------------------
// GEMM2: BM=64, BN=64, 128 threads, micro 8x4 (f32x2, n-packed).
// 1.5 B smem per MAC -> lower LDS-crossbar pressure. grid 1274. PDL.
// ---------------------------------------------------------------------------
#define WMP 72
#define ASP 68
#define WM_FLOATS (64 * WMP)
#define G2_SMEM ((WM_FLOATS + 64 * ASP) * 4)

extern __shared__ float s_g2[];

__global__ __launch_bounds__(128, 4)
void gemm2_kernel(const float* __restrict__ W2,
                  const float* __restrict__ T,
                  const float* __restrict__ b2,
                  float* __restrict__ Kout)
{
    float* Wm = s_g2;
    float* As = s_g2 + WM_FLOATS;

    int b   = blockIdx.z;
    int bm0 = blockIdx.y * 64;
    int bn0 = blockIdx.x * 64;
    int tid = threadIdx.x;
    int tx  = tid & 15;      // 4 n
    int ty  = tid >> 4;      // 0..7 -> 8 m

    // independent prologue: W2 tile 64 x 64
#pragma unroll
    for (int i = 0; i < 8; i++) {
        int idx = tid + i * 128;
        int m   = idx >> 4;
        int k4  = idx & 15;
        int gm  = bm0 + m;
        float4 v = make_float4(0.f, 0.f, 0.f, 0.f);
        if (gm < M2)
            v = *(const float4*)&W2[(size_t)gm * CrD + k4 * 4];
        *(float4*)&Wm[m * WMP + k4 * 4] = v;
    }
    if (tid == 0) cudaTriggerProgrammaticLaunchCompletion();

    cudaGridDependencySynchronize();

#pragma unroll
    for (int i = 0; i < 8; i++) {
        int idx = tid + i * 128;
        int kk  = idx >> 4;
        int n4  = idx & 15;
        float4 v = *(const float4*)&T[((size_t)b * CrD + kk) * Ll + bn0 + n4 * 4];
        float sc = g_scale[kk], sh = g_shift[kk];
        v.x = fmaxf(fmaf(v.x, sc, sh), 0.f);
        v.y = fmaxf(fmaf(v.y, sc, sh), 0.f);
        v.z = fmaxf(fmaf(v.z, sc, sh), 0.f);
        v.w = fmaxf(fmaf(v.w, sc, sh), 0.f);
        *(float4*)&As[kk * ASP + n4 * 4] = v;
    }
    __syncthreads();

    u64t acc[8][2];
#pragma unroll
    for (int i = 0; i < 8; i++) { acc[i][0] = 0ull; acc[i][1] = 0ull; }

#pragma unroll 2
    for (int k4 = 0; k4 < 16; k4++) {
        u64t a[4][2];
#pragma unroll
        for (int r = 0; r < 4; r++) {
            const float* ap = &As[(k4 * 4 + r) * ASP + tx * 4];
            a[r][0] = *(const u64t*)(ap);
            a[r][1] = *(const u64t*)(ap + 2);
        }
#pragma unroll
        for (int i = 0; i < 8; i++) {
            float4 w = *(const float4*)&Wm[(ty * 8 + i) * WMP + k4 * 4];
            u64t wd;
            DUP2(wd, w.x);
            FMA2(acc[i][0], wd, a[0][0]);
            FMA2(acc[i][1], wd, a[0][1]);
            DUP2(wd, w.y);
            FMA2(acc[i][0], wd, a[1][0]);
            FMA2(acc[i][1], wd, a[1][1]);
            DUP2(wd, w.z);
            FMA2(acc[i][0], wd, a[2][0]);
            FMA2(acc[i][1], wd, a[2][1]);
            DUP2(wd, w.w);
            FMA2(acc[i][0], wd, a[3][0]);
            FMA2(acc[i][1], wd, a[3][1]);
        }
    }

#pragma unroll
    for (int i = 0; i < 8; i++) {
        int gm = bm0 + ty * 8 + i;
        if (gm < M2) {
            float bb = b2[gm];
            float4 v = make_float4(lo32(acc[i][0]) + bb, hi32(acc[i][0]) + bb,
                                   lo32(acc[i][1]) + bb, hi32(acc[i][1]) + bb);
            *(float4*)&Kout[((size_t)b * M2 + gm) * Ll + bn0 + tx * 4] = v;
        }
    }
}

// ---------------------------------------------------------------------------
// Involution (byte-identical to R12 winner: unroll 7, PDL).
// ---------------------------------------------------------------------------
extern __shared__ float s_xs[];

__global__ __launch_bounds__(1024, 1)
void involution_kernel(const float* __restrict__ x,
                       const float* __restrict__ kgen,
                       float* __restrict__ out)
{
    float* xs = s_xs;
    float4* xs4 = (float4*)s_xs;

    const int tid = threadIdx.x;
    const int uq  = blockIdx.y;
    const int b   = blockIdx.z;
    const int l0  = blockIdx.x * 64;
    const int y0  = l0 / Ww;

    // independent prologue: stage x tile (input only)
    {
        const float* xb = x + ((size_t)b * Cc + uq * 64) * Ll;
#pragma unroll
        for (int i = 0; i < 8; i++) {
            int idx  = tid + i * 1024;
            int cl   = idx >> 7;
            int rem  = idx & 127;
            int yrel = rem >> 4;
            int f4   = rem & 15;
            int yy   = y0 - 3 + yrel;
            float4 v = make_float4(0.f, 0.f, 0.f, 0.f);
            if (f4 >= 1 && f4 <= 14 && (unsigned)yy < Hh)
                v = *(const float4*)&xb[(size_t)cl * Ll + yy * Ww + (f4 - 1) * 4];
            xs4[idx] = v;
        }
    }
    if (tid == 0) cudaTriggerProgrammaticLaunchCompletion();
    __syncthreads();

    cudaGridDependencySynchronize();

    const int v    = tid >> 6;
    const int lofs = tid & 63;
    const int l    = l0 + lofs;
    const int y    = l / Ww;
    const int xp   = l - y * Ww;
    const int thr_base = (y - y0 + 3) * 64 + (xp + 4);

    const float* kb = kgen + (size_t)b * M2 * Ll + (size_t)v * Ll + l;
    const int*   tv = c_tab.v + v * KKt;

    float acc0 = 0.f, acc1 = 0.f, acc2 = 0.f, acc3 = 0.f;

#pragma unroll 7
    for (int kkp = 0; kkp < KKt; kkp++) {
        float kv = kb[(size_t)(kkp * Gg) * Ll];
        int   a  = tv[kkp] + thr_base;
        acc0 = fmaf(kv, xs[a        ], acc0);
        acc1 = fmaf(kv, xs[a + 8192 ], acc1);
        acc2 = fmaf(kv, xs[a + 16384], acc2);
        acc3 = fmaf(kv, xs[a + 24576], acc3);
    }

    float* ob = out + (size_t)b * Cc * Ll + (size_t)((uq * 4) * Gg + v) * Ll + l;
    ob[0 * Gg * Ll] = acc0;
    ob[1 * Gg * Ll] = acc1;
    ob[2 * Gg * Ll] = acc2;
    ob[3 * Gg * Ll] = acc3;
}

// ---------------------------------------------------------------------------
static void launch_pdl(const void* fn, dim3 grid, dim3 block, size_t smem,
                       void** args)
{
    cudaLaunchConfig_t cfg = {};
    cfg.gridDim = grid;
    cfg.blockDim = block;
    cfg.dynamicSmemBytes = smem;
    cfg.stream = 0;
    cudaLaunchAttribute attr;
    attr.id = cudaLaunchAttributeProgrammaticStreamSerialization;
    attr.val.programmaticStreamSerializationAllowed = 1;
    cfg.attrs = &attr;
    cfg.numAttrs = 1;
    cudaLaunchKernelExC(&cfg, fn, args);
}

extern "C" void kernel_launch(void* const* d_in, const int* in_sizes, int n_in,
                              void* d_out, int out_size)
{
    const float* x     = (const float*)d_in[0];
    const float* w1    = (const float*)d_in[1];
    const float* gamma = (const float*)d_in[3];
    const float* beta  = (const float*)d_in[4];
    const float* w2    = (const float*)d_in[5];
    const float* b2    = (const float*)d_in[6];

    float* out  = (float*)d_out;
    float* kgen = out + OUT_OFF;

    float* t_ptr = nullptr;
    cudaGetSymbolAddress((void**)&t_ptr, g_t);

    cudaFuncSetAttribute(gemm2_kernel,
                         cudaFuncAttributeMaxDynamicSharedMemorySize, G2_SMEM);
    cudaFuncSetAttribute(involution_kernel,
                         cudaFuncAttributeMaxDynamicSharedMemorySize, 32768 * 4);

    // 1) conv1 + BN partial sums
    {
        dim3 grid(Ll / 64, 2, Bn);
        gemm1_kernel<<<grid, 128>>>(w1, x, t_ptr);
    }
    // 2) BN finalize (PDL)
    {
        void* args[] = {(void*)&gamma, (void*)&beta};
        launch_pdl((const void*)bn_finalize_kernel, dim3(1, 1, 1),
                   dim3(256, 1, 1), 0, args);
    }
    // 3) conv2 + fused BN/ReLU (PDL; 8x4 micro, 128 thr)
    {
        void* args[] = {(void*)&w2, (void*)&t_ptr, (void*)&b2, (void*)&kgen};
        launch_pdl((const void*)gemm2_kernel,
                   dim3(Ll / 64, (M2 + 63) / 64, Bn),
                   dim3(128, 1, 1), G2_SMEM, args);
    }
    // 4) involution (PDL)
    {
        void* args[] = {(void*)&x, (void*)&kgen, (void*)&out};
        launch_pdl((const void*)involution_kernel,
                   dim3(Ll / 64, 4, Bn),
                   dim3(1024, 1, 1), 32768 * 4, args);
    }
}